// round 2
// baseline (speedup 1.0000x reference)
#include <cuda_runtime.h>
#include <math.h>

#define BSZ   16384
#define DD    256
#define UU    32
#define NB    8
#define MHD   512
#define RHD   256
#define KCAT  4096   // NB*MHD
#define RNNW  288    // RHD+UU

// ---------------- static device scratch (no allocations allowed) ----------------
__device__ float g_W1fT[(long)NB * DD * MHD];   // [n][d][h] gate-folded W1, k-major for GEMM1 B
__device__ float g_P[(long)NB * RHD * MHD];     // [n][r][h] = Bg @ W2
__device__ float g_Gt[(long)KCAT * DD];         // [(n*512+h)][d] = W_out @ Bg @ W2, k-major for GEMM2 B
__device__ float g_Pb[NB * RHD];                // Bg @ b2
__device__ float g_F[DD * UU];                  // [d][u] = sum_n W_out[n] @ Bu[n]
__device__ float g_biasz[DD];
__device__ float g_UF[(long)BSZ * DD];          // bias_z + dt * ut @ F^T
__device__ float g_X[(long)BSZ * KCAT];         // GELU(LN(zt @ W1f^T + b1)) concat over branches

// ---------------- fold gates into W1, store transposed [n][d][h] ----------------
__global__ void kfold(const float* __restrict__ W1, const float* __restrict__ gates) {
    int idx = blockIdx.x * 256 + threadIdx.x;         // over NB*DD*MHD = 2^20, output-indexed
    int n = idx >> 17;
    int rem = idx & 131071;
    int d = rem >> 9;
    int h = rem & 511;
    float g = gates[n * DD + d];
    float s = 1.0f / (1.0f + expf(-g));
    g_W1fT[idx] = W1[(((long)(n << 9) | h) << 8) | d] * s;
}

// ---------------- generic batched 64x64 tiled SGEMM (precompute only) ----------------
template <bool TSTORE>
__global__ void __launch_bounds__(256) gemm64(
    const float* __restrict__ A, int lda, long sA,
    const float* __restrict__ B, int ldb, long sB,
    float* __restrict__ C, int ldc, long sC, int K)
{
    A += (long)blockIdx.z * sA;
    B += (long)blockIdx.z * sB;
    C += (long)blockIdx.z * sC;
    int bn = blockIdx.x * 64, bm = blockIdx.y * 64;
    __shared__ float As[16][64];
    __shared__ float Bs[16][64];
    int t = threadIdx.x;
    int tr = t >> 4, tc = t & 15;
    float acc[4][4] = {};
    int arow = t >> 2, ak = (t & 3) << 2;
    int bk = t >> 4, boff = (t & 15) << 2;
    for (int k0 = 0; k0 < K; k0 += 16) {
        float4 av = *(const float4*)(A + (long)(bm + arow) * lda + k0 + ak);
        float4 bv = *(const float4*)(B + (long)(k0 + bk) * ldb + bn + boff);
        __syncthreads();
        As[ak + 0][arow] = av.x; As[ak + 1][arow] = av.y;
        As[ak + 2][arow] = av.z; As[ak + 3][arow] = av.w;
        *(float4*)&Bs[bk][boff] = bv;
        __syncthreads();
#pragma unroll
        for (int kk = 0; kk < 16; kk++) {
            float a[4], b[4];
            *(float4*)a = *(float4*)&As[kk][tr << 2];
            *(float4*)b = *(float4*)&Bs[kk][tc << 2];
#pragma unroll
            for (int i = 0; i < 4; i++)
#pragma unroll
                for (int j = 0; j < 4; j++) acc[i][j] = fmaf(a[i], b[j], acc[i][j]);
        }
    }
    if (TSTORE) {
#pragma unroll
        for (int i = 0; i < 4; i++)
#pragma unroll
            for (int j = 0; j < 4; j++)
                C[(long)(bn + (tc << 2) + j) * ldc + bm + (tr << 2) + i] = acc[i][j];
    } else {
#pragma unroll
        for (int i = 0; i < 4; i++) {
            float4 o = make_float4(acc[i][0], acc[i][1], acc[i][2], acc[i][3]);
            *(float4*)(C + (long)(bm + (tr << 2) + i) * ldc + bn + (tc << 2)) = o;
        }
    }
}

// ---------------- tiny precompute kernels ----------------
__global__ void kPb(const float* __restrict__ rnnB, const float* __restrict__ b2) {
    int n = blockIdx.x, r = threadIdx.x;
    const float* a = rnnB + (long)n * RHD * RNNW + (long)r * RNNW;
    const float* b = b2 + n * RHD;
    float s = 0.f;
    for (int i = 0; i < RHD; i++) s = fmaf(a[i], b[i], s);
    g_Pb[n * RHD + r] = s;
}

__global__ void kbiasz(const float* __restrict__ Wout) {
    int d = threadIdx.x;
    float s = 0.f;
    for (int n = 0; n < NB; n++) {
        const float* w = Wout + (long)n * DD * RHD + (long)d * RHD;
        const float* p = g_Pb + n * RHD;
        for (int r = 0; r < RHD; r++) s = fmaf(w[r], p[r], s);
    }
    g_biasz[d] = s;
}

__global__ void kF(const float* __restrict__ Wout, const float* __restrict__ rnnB) {
    int idx = blockIdx.x * 256 + threadIdx.x;     // DD*UU = 8192
    int d = idx >> 5, u = idx & 31;
    float s = 0.f;
    for (int n = 0; n < NB; n++) {
        const float* w = Wout + (long)n * DD * RHD + (long)d * RHD;
        const float* rb = rnnB + (long)n * RHD * RNNW + RHD + u;
        for (int r = 0; r < RHD; r++) s = fmaf(w[r], rb[(long)r * RNNW], s);
    }
    g_F[d * UU + u] = s;
}

// g_UF[b][d] = biasz[d] + dt * sum_u ut[b][u] * F[d][u]
__global__ void __launch_bounds__(256) kUF(const float* __restrict__ ut, const float* __restrict__ dtp) {
    __shared__ float Fs[UU * DD];     // transposed: Fs[u][d]
    __shared__ float uts[64 * UU];
    long b0 = (long)blockIdx.x * 64;
    int t = threadIdx.x;
    for (int idx = t; idx < DD * UU; idx += 256) {
        int d = idx >> 5, u = idx & 31;
        Fs[u * DD + d] = g_F[idx];
    }
    for (int idx = t; idx < 64 * UU; idx += 256) uts[idx] = ut[b0 * UU + idx];
    float dtv = dtp[0];
    float bz = g_biasz[t];
    __syncthreads();
    for (int r = 0; r < 64; r++) {
        float s = 0.f;
#pragma unroll
        for (int u = 0; u < UU; u++) s = fmaf(uts[r * UU + u], Fs[u * DD + t], s);
        g_UF[(b0 + r) * DD + t] = fmaf(dtv, s, bz);
    }
}

// ---------------- K1: X = GELU(LN(zt @ W1f[n]^T + b1)) ----------------
// grid (NB, BSZ/64), 512 threads, 64x512 tile, 8x8 micro
__global__ void __launch_bounds__(512) k1_meas(
    const float* __restrict__ zt, const float* __restrict__ b1,
    const float* __restrict__ lng, const float* __restrict__ lnb)
{
    int n = blockIdx.x;
    long b0 = (long)blockIdx.y * 64;
    const float* Wp = g_W1fT + ((long)n << 17);
    __shared__ float As[16][64];
    __shared__ float Bs[16][512];
    __shared__ float b1s[512], lngs[512], lnbs[512];
    __shared__ float redS[16][8], redQ[16][8];
    int t = threadIdx.x;
    b1s[t]  = b1[n * MHD + t];
    lngs[t] = lng[n * MHD + t];
    lnbs[t] = lnb[n * MHD + t];
    int tr = t >> 6, tc = t & 63;                  // rows tr*8+i, cols tc*8+j
    float acc[8][8];
#pragma unroll
    for (int i = 0; i < 8; i++)
#pragma unroll
        for (int j = 0; j < 8; j++) acc[i][j] = 0.f;
    int arow = t >> 2, ak = (t & 3) << 2;          // A loaders: t < 256
    int bk = t >> 7, boff = (t & 127) << 2;        // B loaders: all 512, 4 rows each
    for (int k0 = 0; k0 < DD; k0 += 16) {
        float4 aR = make_float4(0.f, 0.f, 0.f, 0.f);
        if (t < 256) aR = *(const float4*)(zt + (b0 + arow) * DD + k0 + ak);
        float4 bR[4];
#pragma unroll
        for (int j = 0; j < 4; j++)
            bR[j] = *(const float4*)(Wp + (long)(k0 + bk + 4 * j) * MHD + boff);
        __syncthreads();
        if (t < 256) {
            As[ak + 0][arow] = aR.x; As[ak + 1][arow] = aR.y;
            As[ak + 2][arow] = aR.z; As[ak + 3][arow] = aR.w;
        }
#pragma unroll
        for (int j = 0; j < 4; j++) *(float4*)&Bs[bk + 4 * j][boff] = bR[j];
        __syncthreads();
#pragma unroll
        for (int kk = 0; kk < 16; kk++) {
            float a[8], b[8];
            *(float4*)&a[0] = *(float4*)&As[kk][tr * 8];
            *(float4*)&a[4] = *(float4*)&As[kk][tr * 8 + 4];
            *(float4*)&b[0] = *(float4*)&Bs[kk][tc * 8];
            *(float4*)&b[4] = *(float4*)&Bs[kk][tc * 8 + 4];
#pragma unroll
            for (int i = 0; i < 8; i++)
#pragma unroll
                for (int j = 0; j < 8; j++) acc[i][j] = fmaf(a[i], b[j], acc[i][j]);
        }
    }
    // bias + LN stats (row span 512 = 64 threads sharing tr = warps 2tr, 2tr+1)
    float sums[8], sq[8];
#pragma unroll
    for (int i = 0; i < 8; i++) { sums[i] = 0.f; sq[i] = 0.f; }
#pragma unroll
    for (int i = 0; i < 8; i++)
#pragma unroll
        for (int j = 0; j < 8; j++) {
            float x = acc[i][j] + b1s[tc * 8 + j];
            acc[i][j] = x;
            sums[i] += x;
            sq[i] += x * x;
        }
#pragma unroll
    for (int off = 16; off; off >>= 1)
#pragma unroll
        for (int i = 0; i < 8; i++) {
            sums[i] += __shfl_xor_sync(0xffffffffu, sums[i], off);
            sq[i]   += __shfl_xor_sync(0xffffffffu, sq[i], off);
        }
    int w = t >> 5;
    if ((t & 31) == 0) {
#pragma unroll
        for (int i = 0; i < 8; i++) { redS[w][i] = sums[i]; redQ[w][i] = sq[i]; }
    }
    __syncthreads();
#pragma unroll
    for (int i = 0; i < 8; i++) {
        float s = redS[2 * tr][i] + redS[2 * tr + 1][i];
        float q = redQ[2 * tr][i] + redQ[2 * tr + 1][i];
        float mu = s * (1.f / 512.f);
        float var = q * (1.f / 512.f) - mu * mu;
        float rstd = rsqrtf(var + 1e-5f);
        float o[8];
#pragma unroll
        for (int j = 0; j < 8; j++) {
            float xh = (acc[i][j] - mu) * rstd * lngs[tc * 8 + j] + lnbs[tc * 8 + j];
            o[j] = 0.5f * xh * (1.f + erff(xh * 0.70710678118654752f));
        }
        float* dst = g_X + (b0 + tr * 8 + i) * KCAT + n * MHD + tc * 8;
        *(float4*)dst       = make_float4(o[0], o[1], o[2], o[3]);
        *(float4*)(dst + 4) = make_float4(o[4], o[5], o[6], o[7]);
    }
}

// ---------------- K2: zt1 = X @ Gt + UF ----------------
// grid (DD/128, BSZ/128), 256 threads, 128x128 tile, 8x8 micro, K=4096
__global__ void __launch_bounds__(256) k2_out(float* __restrict__ out)
{
    long bm = (long)blockIdx.y * 128;
    int bn = blockIdx.x * 128;
    __shared__ float As[16][128];
    __shared__ float Bs[16][128];
    int t = threadIdx.x;
    int tr = t >> 4, tc = t & 15;
    float acc[8][8];
#pragma unroll
    for (int i = 0; i < 8; i++)
#pragma unroll
        for (int j = 0; j < 8; j++) acc[i][j] = 0.f;
    for (int k0 = 0; k0 < KCAT; k0 += 16) {
        float4 aR[2], bR[2];
#pragma unroll
        for (int j = 0; j < 2; j++) {
            int idx = t + 256 * j;
            int arow = idx >> 2, ak = (idx & 3) << 2;
            aR[j] = *(const float4*)(g_X + (bm + arow) * KCAT + k0 + ak);
            int bk = idx >> 5, boff = (idx & 31) << 2;
            bR[j] = *(const float4*)(g_Gt + (long)(k0 + bk) * DD + bn + boff);
        }
        __syncthreads();
#pragma unroll
        for (int j = 0; j < 2; j++) {
            int idx = t + 256 * j;
            int arow = idx >> 2, ak = (idx & 3) << 2;
            As[ak + 0][arow] = aR[j].x; As[ak + 1][arow] = aR[j].y;
            As[ak + 2][arow] = aR[j].z; As[ak + 3][arow] = aR[j].w;
            int bk = idx >> 5, boff = (idx & 31) << 2;
            *(float4*)&Bs[bk][boff] = bR[j];
        }
        __syncthreads();
#pragma unroll
        for (int kk = 0; kk < 16; kk++) {
            float a[8], b[8];
            *(float4*)&a[0] = *(float4*)&As[kk][tr * 8];
            *(float4*)&a[4] = *(float4*)&As[kk][tr * 8 + 4];
            *(float4*)&b[0] = *(float4*)&Bs[kk][tc * 8];
            *(float4*)&b[4] = *(float4*)&Bs[kk][tc * 8 + 4];
#pragma unroll
            for (int i = 0; i < 8; i++)
#pragma unroll
                for (int j = 0; j < 8; j++) acc[i][j] = fmaf(a[i], b[j], acc[i][j]);
        }
    }
#pragma unroll
    for (int i = 0; i < 8; i++) {
        long row = bm + tr * 8 + i;
        const float* up = g_UF + row * DD + bn + tc * 8;
        float4 u0 = *(const float4*)up;
        float4 u1 = *(const float4*)(up + 4);
        float* dst = out + row * DD + bn + tc * 8;
        *(float4*)dst = make_float4(acc[i][0] + u0.x, acc[i][1] + u0.y,
                                    acc[i][2] + u0.z, acc[i][3] + u0.w);
        *(float4*)(dst + 4) = make_float4(acc[i][4] + u1.x, acc[i][5] + u1.y,
                                          acc[i][6] + u1.z, acc[i][7] + u1.w);
    }
}

// ---------------- K3: yt1 = zt1 @ C^T + dt * ut @ Dm^T ----------------
// block 128 threads = 4 warps, 8 rows per warp -> 32 rows/block, grid BSZ/32
__global__ void __launch_bounds__(128) kY(
    const float* __restrict__ zt1, float* __restrict__ outY,
    const float* __restrict__ ut, const float* __restrict__ dtp,
    const float* __restrict__ C, const float* __restrict__ Dm)
{
    __shared__ float Cs[20 * 256];
    __shared__ float Dms[20 * 32];
    int t = threadIdx.x;
    for (int i = t; i < 20 * 256; i += 128) Cs[i] = C[i];
    for (int i = t; i < 20 * 32; i += 128) Dms[i] = Dm[i];
    __syncthreads();
    int w = t >> 5, l = t & 31;
    float dtv = dtp[0];
    for (int rr = 0; rr < 8; rr++) {
        long b = (long)blockIdx.x * 32 + w * 8 + rr;
        float zv[8];
#pragma unroll
        for (int i = 0; i < 8; i++) zv[i] = zt1[b * DD + l + 32 * i];
        float dm = 0.f;
        if (l < 20) {
#pragma unroll
            for (int u = 0; u < 32; u++) dm = fmaf(ut[b * UU + u], Dms[l * 32 + u], dm);
            dm *= dtv;
        }
        for (int y = 0; y < 20; y++) {
            float p = 0.f;
#pragma unroll
            for (int i = 0; i < 8; i++) p = fmaf(zv[i], Cs[y * 256 + l + 32 * i], p);
#pragma unroll
            for (int off = 16; off; off >>= 1) p += __shfl_xor_sync(0xffffffffu, p, off);
            if (l == y) outY[b * 20 + y] = p + dm;
        }
    }
}

// ---------------- launch ----------------
extern "C" void kernel_launch(void* const* d_in, const int* in_sizes, int n_in,
                              void* d_out, int out_size) {
    (void)in_sizes; (void)n_in; (void)out_size;
    const float* zt    = (const float*)d_in[0];
    const float* dt    = (const float*)d_in[1];
    const float* ut    = (const float*)d_in[2];
    const float* gates = (const float*)d_in[3];
    const float* W1    = (const float*)d_in[4];
    const float* b1    = (const float*)d_in[5];
    const float* ln_g  = (const float*)d_in[6];
    const float* ln_b  = (const float*)d_in[7];
    const float* W2    = (const float*)d_in[8];
    const float* b2    = (const float*)d_in[9];
    // d_in[10] lam_r, d_in[11] lam_i: unused (lambda drops out at h0=0)
    const float* rnnB  = (const float*)d_in[12];
    const float* Wout  = (const float*)d_in[13];
    const float* C     = (const float*)d_in[14];
    const float* Dm    = (const float*)d_in[15];
    float* out = (float*)d_out;                       // [B*D] zt1 then [B*20] yt1

    float* gP;  cudaGetSymbolAddress((void**)&gP, g_P);
    float* gGt; cudaGetSymbolAddress((void**)&gGt, g_Gt);

    // weight-only precompute (cheap, rerun every call for determinism)
    kfold<<<4096, 256>>>(W1, gates);
    // P[n] = Bg[n] @ W2[n]   (M=256 r, N=512 h, K=256)
    gemm64<false><<<dim3(8, 4, NB), 256>>>(rnnB, RNNW, (long)RHD * RNNW,
                                           W2, MHD, (long)RHD * MHD,
                                           gP, MHD, (long)RHD * MHD, RHD);
    // G[n] = W_out[n] @ P[n], stored transposed into g_Gt[(n*512+h)][d]
    gemm64<true><<<dim3(8, 4, NB), 256>>>(Wout, RHD, (long)DD * RHD,
                                          gP, MHD, (long)RHD * MHD,
                                          gGt, DD, (long)MHD * DD, RHD);
    kPb<<<NB, 256>>>(rnnB, b2);
    kbiasz<<<1, 256>>>(Wout);
    kF<<<32, 256>>>(Wout, rnnB);
    kUF<<<BSZ / 64, 256>>>(ut, dt);

    // main pipeline
    k1_meas<<<dim3(NB, BSZ / 64), 512>>>(zt, b1, ln_g, ln_b);
    k2_out<<<dim3(DD / 128, BSZ / 128), 256>>>(out);
    kY<<<BSZ / 32, 128>>>(out, out + (long)BSZ * DD, ut, dt, C, Dm);
}

// round 4
// speedup vs baseline: 2.4574x; 2.4574x over previous
#include <cuda_runtime.h>
#include <cuda_bf16.h>
#include <math.h>
#include <stdint.h>

#define BSZ   16384
#define DD    256
#define UU    32
#define NB    8
#define MHD   512
#define RHD   256
#define KCAT  4096   // NB*MHD
#define RNNW  288    // RHD+UU

// ---------------- static device scratch (no allocations allowed) ----------------
__device__ __align__(16) __nv_bfloat16 g_W1h[(long)NB * MHD * DD]; // [n][h][d] gate-folded W1 hi
__device__ __align__(16) __nv_bfloat16 g_W1l[(long)NB * MHD * DD]; // lo
__device__ float g_P[(long)NB * RHD * MHD];                        // [n][r][h] = Bg @ W2
__device__ __align__(16) float g_G[(long)DD * KCAT];               // [d][n*512+h]
__device__ __align__(16) __nv_bfloat16 g_Gh[(long)DD * KCAT];
__device__ __align__(16) __nv_bfloat16 g_Gl[(long)DD * KCAT];
__device__ float g_Pb[NB * RHD];
__device__ float g_F[DD * UU];
__device__ float g_biasz[DD];
__device__ __align__(16) float g_UF[(long)BSZ * DD];
__device__ __align__(16) __nv_bfloat16 g_Zh[(long)BSZ * DD];
__device__ __align__(16) __nv_bfloat16 g_Zl[(long)BSZ * DD];
__device__ __align__(16) __nv_bfloat16 g_Xh[(long)BSZ * KCAT];
__device__ __align__(16) __nv_bfloat16 g_Xl[(long)BSZ * KCAT];

// ================= helpers (base-arch only: ldmatrix / mma.sync / cp.async) =================
__device__ __forceinline__ uint32_t smem_u32(const void* p) {
    uint32_t a;
    asm("{ .reg .u64 t; cvta.to.shared.u64 t, %1; cvt.u32.u64 %0, t; }" : "=r"(a) : "l"(p));
    return a;
}
__device__ __forceinline__ void cp16(uint32_t dst, const void* src) {
    asm volatile("cp.async.cg.shared.global [%0], [%1], 16;" :: "r"(dst), "l"(src));
}
#define CP_COMMIT() asm volatile("cp.async.commit_group;")
__device__ __forceinline__ void ldsm4(uint32_t (&r)[4], uint32_t addr) {
    asm volatile("ldmatrix.sync.aligned.m8n8.x4.shared.b16 {%0,%1,%2,%3}, [%4];"
                 : "=r"(r[0]), "=r"(r[1]), "=r"(r[2]), "=r"(r[3]) : "r"(addr));
}
__device__ __forceinline__ void mma16816(float (&d)[4], const uint32_t (&a)[4],
                                         uint32_t b0, uint32_t b1) {
    asm volatile("mma.sync.aligned.m16n8k16.row.col.f32.bf16.bf16.f32 "
                 "{%0,%1,%2,%3}, {%4,%5,%6,%7}, {%8,%9}, {%0,%1,%2,%3};"
                 : "+f"(d[0]), "+f"(d[1]), "+f"(d[2]), "+f"(d[3])
                 : "r"(a[0]), "r"(a[1]), "r"(a[2]), "r"(a[3]), "r"(b0), "r"(b1));
}

// ---------------- fold gates into W1 (natural [n][h][d] layout), split hi/lo ----------------
__global__ void kfold(const float* __restrict__ W1, const float* __restrict__ gates) {
    int idx = blockIdx.x * 256 + threadIdx.x;     // 2^20 over [n][h][d]
    int n = idx >> 17;
    int d = idx & 255;
    float g = gates[n * DD + d];
    float s = 1.0f / (1.0f + expf(-g));
    float v = W1[idx] * s;
    __nv_bfloat16 h = __float2bfloat16(v);
    g_W1h[idx] = h;
    g_W1l[idx] = __float2bfloat16(v - __bfloat162float(h));
}

// ---------------- split zt into bf16 hi/lo ----------------
__global__ void ksplitZ(const float* __restrict__ zt) {
    long i = (long)blockIdx.x * 256 + threadIdx.x;     // BSZ*DD = 4M
    float v = zt[i];
    __nv_bfloat16 h = __float2bfloat16(v);
    g_Zh[i] = h;
    g_Zl[i] = __float2bfloat16(v - __bfloat162float(h));
}

// ---------------- split G into bf16 hi/lo ----------------
__global__ void kGconv() {
    long i = (long)blockIdx.x * 256 + threadIdx.x;     // DD*KCAT = 2^20
    float v = g_G[i];
    __nv_bfloat16 h = __float2bfloat16(v);
    g_Gh[i] = h;
    g_Gl[i] = __float2bfloat16(v - __bfloat162float(h));
}

// ---------------- batched 64x64 tiled SGEMM (fp32 precompute only) ----------------
__global__ void __launch_bounds__(256) gemm64(
    const float* __restrict__ A, int lda, long sA,
    const float* __restrict__ B, int ldb, long sB,
    float* __restrict__ C, int ldc, long sC, int K)
{
    A += (long)blockIdx.z * sA;
    B += (long)blockIdx.z * sB;
    C += (long)blockIdx.z * sC;
    int bn = blockIdx.x * 64, bm = blockIdx.y * 64;
    __shared__ float As[16][64];
    __shared__ float Bs[16][64];
    int t = threadIdx.x;
    int tr = t >> 4, tc = t & 15;
    float acc[4][4] = {};
    int arow = t >> 2, ak = (t & 3) << 2;
    int bk = t >> 4, boff = (t & 15) << 2;
    for (int k0 = 0; k0 < K; k0 += 16) {
        float4 av = *(const float4*)(A + (long)(bm + arow) * lda + k0 + ak);
        float4 bv = *(const float4*)(B + (long)(k0 + bk) * ldb + bn + boff);
        __syncthreads();
        As[ak + 0][arow] = av.x; As[ak + 1][arow] = av.y;
        As[ak + 2][arow] = av.z; As[ak + 3][arow] = av.w;
        *(float4*)&Bs[bk][boff] = bv;
        __syncthreads();
#pragma unroll
        for (int kk = 0; kk < 16; kk++) {
            float a[4], b[4];
            *(float4*)a = *(float4*)&As[kk][tr << 2];
            *(float4*)b = *(float4*)&Bs[kk][tc << 2];
#pragma unroll
            for (int i = 0; i < 4; i++)
#pragma unroll
                for (int j = 0; j < 4; j++) acc[i][j] = fmaf(a[i], b[j], acc[i][j]);
        }
    }
#pragma unroll
    for (int i = 0; i < 4; i++) {
        float4 o = make_float4(acc[i][0], acc[i][1], acc[i][2], acc[i][3]);
        *(float4*)(C + (long)(bm + (tr << 2) + i) * ldc + bn + (tc << 2)) = o;
    }
}

// ---------------- tiny precompute kernels (warp-per-output) ----------------
__global__ void kPb(const float* __restrict__ rnnB, const float* __restrict__ b2) {
    int g = blockIdx.x * 8 + (threadIdx.x >> 5);      // 2048 outputs
    int lane = threadIdx.x & 31;
    int n = g >> 8, r = g & 255;
    const float* a = rnnB + (long)n * RHD * RNNW + (long)r * RNNW;
    const float* b = b2 + n * RHD;
    float s = 0.f;
#pragma unroll
    for (int i = 0; i < 8; i++) s = fmaf(a[lane + 32 * i], b[lane + 32 * i], s);
#pragma unroll
    for (int off = 16; off; off >>= 1) s += __shfl_xor_sync(0xffffffffu, s, off);
    if (lane == 0) g_Pb[g] = s;
}

__global__ void kbiasz(const float* __restrict__ Wout) {
    int d = blockIdx.x * 8 + (threadIdx.x >> 5);      // 256 outputs
    int lane = threadIdx.x & 31;
    float s = 0.f;
#pragma unroll
    for (int i = 0; i < 64; i++) {
        int idx = lane + 32 * i;                       // 0..2047
        int n = idx >> 8, r = idx & 255;
        s = fmaf(Wout[(long)n * DD * RHD + (long)d * RHD + r], g_Pb[n * RHD + r], s);
    }
#pragma unroll
    for (int off = 16; off; off >>= 1) s += __shfl_xor_sync(0xffffffffu, s, off);
    if (lane == 0) g_biasz[d] = s;
}

__global__ void kF(const float* __restrict__ Wout, const float* __restrict__ rnnB) {
    int g = blockIdx.x * 8 + (threadIdx.x >> 5);      // 8192 outputs
    int lane = threadIdx.x & 31;
    int d = g >> 5, u = g & 31;
    float s = 0.f;
#pragma unroll
    for (int i = 0; i < 64; i++) {
        int idx = lane + 32 * i;
        int n = idx >> 8, r = idx & 255;
        s = fmaf(Wout[(long)n * DD * RHD + (long)d * RHD + r],
                 rnnB[(long)n * RHD * RNNW + (long)r * RNNW + RHD + u], s);
    }
#pragma unroll
    for (int off = 16; off; off >>= 1) s += __shfl_xor_sync(0xffffffffu, s, off);
    if (lane == 0) g_F[d * UU + u] = s;
}

// g_UF[b][d] = biasz[d] + dt * sum_u ut[b][u] * F[d][u]
__global__ void __launch_bounds__(256) kUF(const float* __restrict__ ut, const float* __restrict__ dtp) {
    __shared__ float Fs[UU * DD];
    __shared__ float uts[64 * UU];
    long b0 = (long)blockIdx.x * 64;
    int t = threadIdx.x;
    for (int idx = t; idx < DD * UU; idx += 256) {
        int d = idx >> 5, u = idx & 31;
        Fs[u * DD + d] = g_F[idx];
    }
    for (int idx = t; idx < 64 * UU; idx += 256) uts[idx] = ut[b0 * UU + idx];
    float dtv = dtp[0];
    float bz = g_biasz[t];
    __syncthreads();
    for (int r = 0; r < 64; r++) {
        float s = 0.f;
#pragma unroll
        for (int u = 0; u < UU; u++) s = fmaf(uts[r * UU + u], Fs[u * DD + t], s);
        g_UF[(b0 + r) * DD + t] = fmaf(dtv, s, bz);
    }
}

// ============ K1: X = split(GELU(LN(zt @ W1f[n]^T + b1))) via mma.sync bf16 hi/lo ============
// CTA 64x512, 512 threads (warp grid 2x8, warp tile 32x64), K=256 in 8 chunks of 32.
// dynamic smem: A[ver][buf] 4KB each (16KB) + B[ver][buf] 32KB each (128KB) = 147456 B
#define K1_SMEM 147456

__global__ void __launch_bounds__(512) k1_mma(
    const float* __restrict__ b1, const float* __restrict__ lng, const float* __restrict__ lnb)
{
    extern __shared__ __align__(128) char sm1[];
    const uint32_t sb = smem_u32(sm1);
    const int t = threadIdx.x;
    const int lane = t & 31, wid = t >> 5;
    const int wy = wid >> 3, wx = wid & 7;
    const int n = blockIdx.x;
    const long b0 = (long)blockIdx.y * 64;

    __shared__ float b1s[512], lngs[512], lnbs[512];
    __shared__ float redS[8][64], redQ[8][64];
    __shared__ float muS[64], rsS[64];

    b1s[t]  = b1[n * MHD + t];
    lngs[t] = lng[n * MHD + t];
    lnbs[t] = lnb[n * MHD + t];

    const __nv_bfloat16* W1hB = g_W1h + ((long)n << 17);
    const __nv_bfloat16* W1lB = g_W1l + ((long)n << 17);

    // loader lambda: chunk c into buffer buf
    auto load_chunk = [&](int c, int buf) {
        int kb = c * 32;
        {   // A: 512 cp.async (ver from t>>8)
            int ver = t >> 8, i = t & 255, row = i >> 2, cu = i & 3;
            const __nv_bfloat16* src = (ver ? g_Zl : g_Zh) + (b0 + row) * DD + kb + cu * 8;
            uint32_t dst = sb + ver * 8192 + buf * 4096 + row * 64 + ((cu ^ ((row >> 1) & 3)) << 4);
            cp16(dst, src);
        }
#pragma unroll
        for (int j = 0; j < 8; j++) {   // B: 4096 cp.async
            int id = t + 512 * j;
            int ver = id >> 11, i = id & 2047, row = i >> 2, cu = i & 3;
            const __nv_bfloat16* src = (ver ? W1lB : W1hB) + (long)row * DD + kb + cu * 8;
            uint32_t dst = sb + 16384 + ver * 65536 + buf * 32768 + row * 64
                         + ((cu ^ ((row >> 1) & 3)) << 4);
            cp16(dst, src);
        }
    };

    float acc[2][8][4];
#pragma unroll
    for (int a = 0; a < 2; a++)
#pragma unroll
        for (int b = 0; b < 8; b++)
#pragma unroll
            for (int c = 0; c < 4; c++) acc[a][b][c] = 0.f;

    load_chunk(0, 0);
    CP_COMMIT();
    for (int c = 0; c < 8; c++) {
        int buf = c & 1;
        if (c + 1 < 8) {
            load_chunk(c + 1, (c + 1) & 1);
            CP_COMMIT();
            asm volatile("cp.async.wait_group 1;");
        } else {
            asm volatile("cp.async.wait_group 0;");
        }
        __syncthreads();
        uint32_t aH = sb + buf * 4096;
        uint32_t aL = aH + 8192;
        uint32_t bH = sb + 16384 + buf * 32768;
        uint32_t bL = bH + 65536;
#pragma unroll
        for (int k16 = 0; k16 < 2; k16++) {
            uint32_t ah[2][4], al[2][4];
#pragma unroll
            for (int rf = 0; rf < 2; rf++) {
                int r = wy * 32 + rf * 16 + (lane & 15);
                int cu = k16 * 2 + (lane >> 4);
                uint32_t off = r * 64 + ((cu ^ ((r >> 1) & 3)) << 4);
                ldsm4(ah[rf], aH + off);
                ldsm4(al[rf], aL + off);
            }
#pragma unroll
            for (int bf = 0; bf < 4; bf++) {
                int rb = wx * 64 + bf * 16 + (lane & 15);
                int cu = k16 * 2 + (lane >> 4);
                uint32_t off = rb * 64 + ((cu ^ ((rb >> 1) & 3)) << 4);
                uint32_t bh[4], bl[4];
                ldsm4(bh, bH + off);
                ldsm4(bl, bL + off);
#pragma unroll
                for (int rf = 0; rf < 2; rf++) {
                    mma16816(acc[rf][2 * bf],     ah[rf], bh[0], bh[2]);
                    mma16816(acc[rf][2 * bf + 1], ah[rf], bh[1], bh[3]);
                    mma16816(acc[rf][2 * bf],     ah[rf], bl[0], bl[2]);
                    mma16816(acc[rf][2 * bf + 1], ah[rf], bl[1], bl[3]);
                    mma16816(acc[rf][2 * bf],     al[rf], bh[0], bh[2]);
                    mma16816(acc[rf][2 * bf + 1], al[rf], bh[1], bh[3]);
                }
            }
        }
        __syncthreads();
    }

    // ---- bias + LN stats ----
    float sums[2][2] = {{0.f, 0.f}, {0.f, 0.f}};
    float sqs[2][2]  = {{0.f, 0.f}, {0.f, 0.f}};
#pragma unroll
    for (int rf = 0; rf < 2; rf++)
#pragma unroll
        for (int nf = 0; nf < 8; nf++)
#pragma unroll
            for (int h = 0; h < 2; h++)
#pragma unroll
                for (int p = 0; p < 2; p++) {
                    int col = wx * 64 + nf * 8 + (lane & 3) * 2 + p;
                    float x = acc[rf][nf][h * 2 + p] + b1s[col];
                    acc[rf][nf][h * 2 + p] = x;
                    sums[rf][h] += x;
                    sqs[rf][h]  += x * x;
                }
#pragma unroll
    for (int rf = 0; rf < 2; rf++)
#pragma unroll
        for (int h = 0; h < 2; h++) {
            sums[rf][h] += __shfl_xor_sync(0xffffffffu, sums[rf][h], 1);
            sums[rf][h] += __shfl_xor_sync(0xffffffffu, sums[rf][h], 2);
            sqs[rf][h]  += __shfl_xor_sync(0xffffffffu, sqs[rf][h], 1);
            sqs[rf][h]  += __shfl_xor_sync(0xffffffffu, sqs[rf][h], 2);
        }
    if ((lane & 3) == 0) {
#pragma unroll
        for (int rf = 0; rf < 2; rf++)
#pragma unroll
            for (int h = 0; h < 2; h++) {
                int r = wy * 32 + rf * 16 + h * 8 + (lane >> 2);
                redS[wx][r] = sums[rf][h];
                redQ[wx][r] = sqs[rf][h];
            }
    }
    __syncthreads();
    if (t < 64) {
        float s = 0.f, q = 0.f;
#pragma unroll
        for (int w = 0; w < 8; w++) { s += redS[w][t]; q += redQ[w][t]; }
        float mu = s * (1.f / 512.f);
        float var = q * (1.f / 512.f) - mu * mu;
        muS[t] = mu;
        rsS[t] = rsqrtf(var + 1e-5f);
    }
    __syncthreads();

    // ---- LN scale/shift + GELU + bf16 split + store ----
#pragma unroll
    for (int rf = 0; rf < 2; rf++)
#pragma unroll
        for (int h = 0; h < 2; h++) {
            int r = wy * 32 + rf * 16 + h * 8 + (lane >> 2);
            float mu = muS[r], rs = rsS[r];
            long grow = b0 + r;
            __nv_bfloat16* xh = g_Xh + grow * KCAT + (long)n * MHD;
            __nv_bfloat16* xl = g_Xl + grow * KCAT + (long)n * MHD;
#pragma unroll
            for (int nf = 0; nf < 8; nf++) {
                int col = wx * 64 + nf * 8 + (lane & 3) * 2;
                float x0 = (acc[rf][nf][h * 2 + 0] - mu) * rs * lngs[col]     + lnbs[col];
                float x1 = (acc[rf][nf][h * 2 + 1] - mu) * rs * lngs[col + 1] + lnbs[col + 1];
                x0 = 0.5f * x0 * (1.f + erff(x0 * 0.70710678118654752f));
                x1 = 0.5f * x1 * (1.f + erff(x1 * 0.70710678118654752f));
                __nv_bfloat162 hp = __floats2bfloat162_rn(x0, x1);
                __nv_bfloat162 lp = __floats2bfloat162_rn(x0 - __low2float(hp),
                                                          x1 - __high2float(hp));
                *(__nv_bfloat162*)(xh + col) = hp;
                *(__nv_bfloat162*)(xl + col) = lp;
            }
        }
}

// ============ K2: zt1 = X @ G^T + UF via mma.sync bf16 hi/lo ============
// CTA 128x256, 512 threads (warp grid 4x4, warp tile 32x64), K=4096 in 128 chunks of 32.
// dynamic smem: A 8KB x4 (32KB) + B 16KB x4 (64KB) = 98304 B
#define K2_SMEM 98304

__global__ void __launch_bounds__(512) k2_mma(float* __restrict__ out)
{
    extern __shared__ __align__(128) char sm2[];
    const uint32_t sb = smem_u32(sm2);
    const int t = threadIdx.x;
    const int lane = t & 31, wid = t >> 5;
    const int wy = wid >> 2, wx = wid & 3;
    const long bm = (long)blockIdx.x * 128;

    auto load_chunk = [&](int c, int buf) {
        int kb = c * 32;
#pragma unroll
        for (int j = 0; j < 2; j++) {   // A: 1024 cp.async
            int id = t + 512 * j;
            int ver = id >> 9, i = id & 511, row = i >> 2, cu = i & 3;
            const __nv_bfloat16* src = (ver ? g_Xl : g_Xh) + (bm + row) * (long)KCAT + kb + cu * 8;
            uint32_t dst = sb + ver * 16384 + buf * 8192 + row * 64
                         + ((cu ^ ((row >> 1) & 3)) << 4);
            cp16(dst, src);
        }
#pragma unroll
        for (int j = 0; j < 4; j++) {   // B: 2048 cp.async
            int id = t + 512 * j;
            int ver = id >> 10, i = id & 1023, row = i >> 2, cu = i & 3;
            const __nv_bfloat16* src = (ver ? g_Gl : g_Gh) + (long)row * KCAT + kb + cu * 8;
            uint32_t dst = sb + 32768 + ver * 32768 + buf * 16384 + row * 64
                         + ((cu ^ ((row >> 1) & 3)) << 4);
            cp16(dst, src);
        }
    };

    float acc[2][8][4];
#pragma unroll
    for (int a = 0; a < 2; a++)
#pragma unroll
        for (int b = 0; b < 8; b++)
#pragma unroll
            for (int c = 0; c < 4; c++) acc[a][b][c] = 0.f;

    load_chunk(0, 0);
    CP_COMMIT();
    for (int c = 0; c < 128; c++) {
        int buf = c & 1;
        if (c + 1 < 128) {
            load_chunk(c + 1, (c + 1) & 1);
            CP_COMMIT();
            asm volatile("cp.async.wait_group 1;");
        } else {
            asm volatile("cp.async.wait_group 0;");
        }
        __syncthreads();
        uint32_t aH = sb + buf * 8192;
        uint32_t aL = aH + 16384;
        uint32_t bH = sb + 32768 + buf * 16384;
        uint32_t bL = bH + 32768;
#pragma unroll
        for (int k16 = 0; k16 < 2; k16++) {
            uint32_t ah[2][4], al[2][4];
#pragma unroll
            for (int rf = 0; rf < 2; rf++) {
                int r = wy * 32 + rf * 16 + (lane & 15);
                int cu = k16 * 2 + (lane >> 4);
                uint32_t off = r * 64 + ((cu ^ ((r >> 1) & 3)) << 4);
                ldsm4(ah[rf], aH + off);
                ldsm4(al[rf], aL + off);
            }
#pragma unroll
            for (int bf = 0; bf < 4; bf++) {
                int rb = wx * 64 + bf * 16 + (lane & 15);
                int cu = k16 * 2 + (lane >> 4);
                uint32_t off = rb * 64 + ((cu ^ ((rb >> 1) & 3)) << 4);
                uint32_t bh[4], bl[4];
                ldsm4(bh, bH + off);
                ldsm4(bl, bL + off);
#pragma unroll
                for (int rf = 0; rf < 2; rf++) {
                    mma16816(acc[rf][2 * bf],     ah[rf], bh[0], bh[2]);
                    mma16816(acc[rf][2 * bf + 1], ah[rf], bh[1], bh[3]);
                    mma16816(acc[rf][2 * bf],     ah[rf], bl[0], bl[2]);
                    mma16816(acc[rf][2 * bf + 1], ah[rf], bl[1], bl[3]);
                    mma16816(acc[rf][2 * bf],     al[rf], bh[0], bh[2]);
                    mma16816(acc[rf][2 * bf + 1], al[rf], bh[1], bh[3]);
                }
            }
        }
        __syncthreads();
    }

    // epilogue: + UF, store fp32
#pragma unroll
    for (int rf = 0; rf < 2; rf++)
#pragma unroll
        for (int h = 0; h < 2; h++) {
            long row = bm + wy * 32 + rf * 16 + h * 8 + (lane >> 2);
#pragma unroll
            for (int nf = 0; nf < 8; nf++) {
                int col = wx * 64 + nf * 8 + (lane & 3) * 2;
                float2 u = *(const float2*)(g_UF + row * DD + col);
                float2 o;
                o.x = acc[rf][nf][h * 2 + 0] + u.x;
                o.y = acc[rf][nf][h * 2 + 1] + u.y;
                *(float2*)(out + row * DD + col) = o;
            }
        }
}

// ---------------- K3: yt1 = zt1 @ C^T + dt * ut @ Dm^T ----------------
__global__ void __launch_bounds__(128) kY(
    const float* __restrict__ zt1, float* __restrict__ outY,
    const float* __restrict__ ut, const float* __restrict__ dtp,
    const float* __restrict__ C, const float* __restrict__ Dm)
{
    __shared__ float Cs[20 * 256];
    __shared__ float Dms[20 * 32];
    int t = threadIdx.x;
    for (int i = t; i < 20 * 256; i += 128) Cs[i] = C[i];
    for (int i = t; i < 20 * 32; i += 128) Dms[i] = Dm[i];
    __syncthreads();
    int w = t >> 5, l = t & 31;
    float dtv = dtp[0];
    for (int rr = 0; rr < 8; rr++) {
        long b = (long)blockIdx.x * 32 + w * 8 + rr;
        float zv[8];
#pragma unroll
        for (int i = 0; i < 8; i++) zv[i] = zt1[b * DD + l + 32 * i];
        float dm = 0.f;
        if (l < 20) {
#pragma unroll
            for (int u = 0; u < 32; u++) dm = fmaf(ut[b * UU + u], Dms[l * 32 + u], dm);
            dm *= dtv;
        }
        for (int y = 0; y < 20; y++) {
            float p = 0.f;
#pragma unroll
            for (int i = 0; i < 8; i++) p = fmaf(zv[i], Cs[y * 256 + l + 32 * i], p);
#pragma unroll
            for (int off = 16; off; off >>= 1) p += __shfl_xor_sync(0xffffffffu, p, off);
            if (l == y) outY[b * 20 + y] = p + dm;
        }
    }
}

// ---------------- launch ----------------
extern "C" void kernel_launch(void* const* d_in, const int* in_sizes, int n_in,
                              void* d_out, int out_size) {
    (void)in_sizes; (void)n_in; (void)out_size;
    const float* zt    = (const float*)d_in[0];
    const float* dt    = (const float*)d_in[1];
    const float* ut    = (const float*)d_in[2];
    const float* gates = (const float*)d_in[3];
    const float* W1    = (const float*)d_in[4];
    const float* b1    = (const float*)d_in[5];
    const float* ln_g  = (const float*)d_in[6];
    const float* ln_b  = (const float*)d_in[7];
    const float* W2    = (const float*)d_in[8];
    const float* b2    = (const float*)d_in[9];
    // d_in[10] lam_r, d_in[11] lam_i unused (lambda drops out at h0=0)
    const float* rnnB  = (const float*)d_in[12];
    const float* Wout  = (const float*)d_in[13];
    const float* C     = (const float*)d_in[14];
    const float* Dm    = (const float*)d_in[15];
    float* out = (float*)d_out;                    // [B*D] zt1 then [B*20] yt1

    float* gP; cudaGetSymbolAddress((void**)&gP, g_P);
    float* gG; cudaGetSymbolAddress((void**)&gG, g_G);

    cudaFuncSetAttribute(k1_mma, cudaFuncAttributeMaxDynamicSharedMemorySize, K1_SMEM);
    cudaFuncSetAttribute(k2_mma, cudaFuncAttributeMaxDynamicSharedMemorySize, K2_SMEM);

    // weight precompute
    kfold<<<4096, 256>>>(W1, gates);
    ksplitZ<<<16384, 256>>>(zt);
    // P[n] = Bg[n] @ W2[n]
    gemm64<<<dim3(8, 4, NB), 256>>>(rnnB, RNNW, (long)RHD * RNNW,
                                    W2, MHD, (long)RHD * MHD,
                                    gP, MHD, (long)RHD * MHD, RHD);
    // G[d][n*512+h] = W_out[n] @ P[n]
    gemm64<<<dim3(8, 4, NB), 256>>>(Wout, RHD, (long)DD * RHD,
                                    gP, MHD, (long)RHD * MHD,
                                    gG, KCAT, (long)MHD, RHD);
    kGconv<<<4096, 256>>>();
    kPb<<<256, 256>>>(rnnB, b2);
    kbiasz<<<32, 256>>>(Wout);
    kF<<<1024, 256>>>(Wout, rnnB);
    kUF<<<BSZ / 64, 256>>>(ut, dt);

    // main pipeline
    k1_mma<<<dim3(NB, BSZ / 64), 512, K1_SMEM>>>(b1, ln_g, ln_b);
    k2_mma<<<128, 512, K2_SMEM>>>(out);
    kY<<<BSZ / 32, 128>>>(out, out + (long)BSZ * DD, ut, dt, C, Dm);
}

// round 5
// speedup vs baseline: 2.8720x; 1.1687x over previous
#include <cuda_runtime.h>
#include <cuda_fp16.h>
#include <math.h>
#include <stdint.h>

#define BSZ   16384
#define DD    256
#define UU    32
#define NB    8
#define MHD   512
#define RHD   256
#define KCAT  4096   // NB*MHD
#define RNNW  288    // RHD+UU

// ---------------- static device scratch (no allocations allowed) ----------------
__device__ __align__(16) __half g_W1h[(long)NB * MHD * DD]; // [n][h][d] gate-folded W1 hi
__device__ __align__(16) __half g_W1l[(long)NB * MHD * DD]; // lo
__device__ float g_P[(long)NB * RHD * MHD];                 // [n][r][h] = Bg @ W2
__device__ __align__(16) float g_G[(long)DD * KCAT];        // [d][n*512+h]
__device__ __align__(16) __half g_Gh[(long)DD * KCAT];
__device__ __align__(16) __half g_Gl[(long)DD * KCAT];
__device__ float g_Pb[NB * RHD];
__device__ float g_F[DD * UU];
__device__ float g_biasz[DD];
__device__ __align__(16) float g_UF[(long)BSZ * DD];
__device__ __align__(16) __half g_Zh[(long)BSZ * DD];
__device__ __align__(16) __half g_Zl[(long)BSZ * DD];
__device__ __align__(16) __half g_Xh[(long)BSZ * KCAT];     // single fp16 X (2^-12 quant)

// ================= helpers (base-arch only: ldmatrix / mma.sync / cp.async) =================
__device__ __forceinline__ uint32_t smem_u32(const void* p) {
    uint32_t a;
    asm("{ .reg .u64 t; cvta.to.shared.u64 t, %1; cvt.u32.u64 %0, t; }" : "=r"(a) : "l"(p));
    return a;
}
__device__ __forceinline__ void cp16(uint32_t dst, const void* src) {
    asm volatile("cp.async.cg.shared.global [%0], [%1], 16;" :: "r"(dst), "l"(src));
}
#define CP_COMMIT() asm volatile("cp.async.commit_group;")
__device__ __forceinline__ void ldsm4(uint32_t (&r)[4], uint32_t addr) {
    asm volatile("ldmatrix.sync.aligned.m8n8.x4.shared.b16 {%0,%1,%2,%3}, [%4];"
                 : "=r"(r[0]), "=r"(r[1]), "=r"(r[2]), "=r"(r[3]) : "r"(addr));
}
__device__ __forceinline__ void mma16816(float (&d)[4], const uint32_t (&a)[4],
                                         uint32_t b0, uint32_t b1) {
    asm volatile("mma.sync.aligned.m16n8k16.row.col.f32.f16.f16.f32 "
                 "{%0,%1,%2,%3}, {%4,%5,%6,%7}, {%8,%9}, {%0,%1,%2,%3};"
                 : "+f"(d[0]), "+f"(d[1]), "+f"(d[2]), "+f"(d[3])
                 : "r"(a[0]), "r"(a[1]), "r"(a[2]), "r"(a[3]), "r"(b0), "r"(b1));
}

// ---------------- fold gates into W1 ([n][h][d]), split fp16 hi/lo ----------------
__global__ void kfold(const float* __restrict__ W1, const float* __restrict__ gates) {
    int idx = blockIdx.x * 256 + threadIdx.x;     // 2^20 over [n][h][d]
    int n = idx >> 17;
    int d = idx & 255;
    float g = gates[n * DD + d];
    float s = 1.0f / (1.0f + expf(-g));
    float v = W1[idx] * s;
    __half h = __float2half_rn(v);
    g_W1h[idx] = h;
    g_W1l[idx] = __float2half_rn(v - __half2float(h));
}

// ---------------- split zt into fp16 hi/lo ----------------
__global__ void ksplitZ(const float* __restrict__ zt) {
    long i = (long)blockIdx.x * 256 + threadIdx.x;     // BSZ*DD = 4M
    float v = zt[i];
    __half h = __float2half_rn(v);
    g_Zh[i] = h;
    g_Zl[i] = __float2half_rn(v - __half2float(h));
}

// ---------------- split G into fp16 hi/lo ----------------
__global__ void kGconv() {
    long i = (long)blockIdx.x * 256 + threadIdx.x;     // DD*KCAT = 2^20
    float v = g_G[i];
    __half h = __float2half_rn(v);
    g_Gh[i] = h;
    g_Gl[i] = __float2half_rn(v - __half2float(h));
}

// ---------------- batched 64x64 tiled SGEMM (fp32 precompute only) ----------------
__global__ void __launch_bounds__(256) gemm64(
    const float* __restrict__ A, int lda, long sA,
    const float* __restrict__ B, int ldb, long sB,
    float* __restrict__ C, int ldc, long sC, int K)
{
    A += (long)blockIdx.z * sA;
    B += (long)blockIdx.z * sB;
    C += (long)blockIdx.z * sC;
    int bn = blockIdx.x * 64, bm = blockIdx.y * 64;
    __shared__ float As[16][64];
    __shared__ float Bs[16][64];
    int t = threadIdx.x;
    int tr = t >> 4, tc = t & 15;
    float acc[4][4] = {};
    int arow = t >> 2, ak = (t & 3) << 2;
    int bk = t >> 4, boff = (t & 15) << 2;
    for (int k0 = 0; k0 < K; k0 += 16) {
        float4 av = *(const float4*)(A + (long)(bm + arow) * lda + k0 + ak);
        float4 bv = *(const float4*)(B + (long)(k0 + bk) * ldb + bn + boff);
        __syncthreads();
        As[ak + 0][arow] = av.x; As[ak + 1][arow] = av.y;
        As[ak + 2][arow] = av.z; As[ak + 3][arow] = av.w;
        *(float4*)&Bs[bk][boff] = bv;
        __syncthreads();
#pragma unroll
        for (int kk = 0; kk < 16; kk++) {
            float a[4], b[4];
            *(float4*)a = *(float4*)&As[kk][tr << 2];
            *(float4*)b = *(float4*)&Bs[kk][tc << 2];
#pragma unroll
            for (int i = 0; i < 4; i++)
#pragma unroll
                for (int j = 0; j < 4; j++) acc[i][j] = fmaf(a[i], b[j], acc[i][j]);
        }
    }
#pragma unroll
    for (int i = 0; i < 4; i++) {
        float4 o = make_float4(acc[i][0], acc[i][1], acc[i][2], acc[i][3]);
        *(float4*)(C + (long)(bm + (tr << 2) + i) * ldc + bn + (tc << 2)) = o;
    }
}

// ---------------- tiny precompute kernels (warp-per-output) ----------------
__global__ void kPb(const float* __restrict__ rnnB, const float* __restrict__ b2) {
    int g = blockIdx.x * 8 + (threadIdx.x >> 5);      // 2048 outputs
    int lane = threadIdx.x & 31;
    int n = g >> 8, r = g & 255;
    const float* a = rnnB + (long)n * RHD * RNNW + (long)r * RNNW;
    const float* b = b2 + n * RHD;
    float s = 0.f;
#pragma unroll
    for (int i = 0; i < 8; i++) s = fmaf(a[lane + 32 * i], b[lane + 32 * i], s);
#pragma unroll
    for (int off = 16; off; off >>= 1) s += __shfl_xor_sync(0xffffffffu, s, off);
    if (lane == 0) g_Pb[g] = s;
}

__global__ void kbiasz(const float* __restrict__ Wout) {
    int d = blockIdx.x * 8 + (threadIdx.x >> 5);      // 256 outputs
    int lane = threadIdx.x & 31;
    float s = 0.f;
#pragma unroll
    for (int i = 0; i < 64; i++) {
        int idx = lane + 32 * i;                       // 0..2047
        int n = idx >> 8, r = idx & 255;
        s = fmaf(Wout[(long)n * DD * RHD + (long)d * RHD + r], g_Pb[n * RHD + r], s);
    }
#pragma unroll
    for (int off = 16; off; off >>= 1) s += __shfl_xor_sync(0xffffffffu, s, off);
    if (lane == 0) g_biasz[d] = s;
}

__global__ void kF(const float* __restrict__ Wout, const float* __restrict__ rnnB) {
    int g = blockIdx.x * 8 + (threadIdx.x >> 5);      // 8192 outputs
    int lane = threadIdx.x & 31;
    int d = g >> 5, u = g & 31;
    float s = 0.f;
#pragma unroll
    for (int i = 0; i < 64; i++) {
        int idx = lane + 32 * i;
        int n = idx >> 8, r = idx & 255;
        s = fmaf(Wout[(long)n * DD * RHD + (long)d * RHD + r],
                 rnnB[(long)n * RHD * RNNW + (long)r * RNNW + RHD + u], s);
    }
#pragma unroll
    for (int off = 16; off; off >>= 1) s += __shfl_xor_sync(0xffffffffu, s, off);
    if (lane == 0) g_F[d * UU + u] = s;
}

// g_UF[b][d] = biasz[d] + dt * sum_u ut[b][u] * F[d][u]
__global__ void __launch_bounds__(256) kUF(const float* __restrict__ ut, const float* __restrict__ dtp) {
    __shared__ float Fs[UU * DD];
    __shared__ float uts[64 * UU];
    long b0 = (long)blockIdx.x * 64;
    int t = threadIdx.x;
    for (int idx = t; idx < DD * UU; idx += 256) {
        int d = idx >> 5, u = idx & 31;
        Fs[u * DD + d] = g_F[idx];
    }
    for (int idx = t; idx < 64 * UU; idx += 256) uts[idx] = ut[b0 * UU + idx];
    float dtv = dtp[0];
    float bz = g_biasz[t];
    __syncthreads();
    for (int r = 0; r < 64; r++) {
        float s = 0.f;
#pragma unroll
        for (int u = 0; u < UU; u++) s = fmaf(uts[r * UU + u], Fs[u * DD + t], s);
        g_UF[(b0 + r) * DD + t] = fmaf(dtv, s, bz);
    }
}

// ============ K1: Xh = fp16(GELU(LN(zt @ W1f[n]^T + b1))) via mma.sync fp16 3-term ============
// CTA 64x512, 512 threads (warp grid 2x8, warp tile 32x64), K=256 in 8 chunks of 32.
// smem: A[ver][buf] 4KB (16KB) + B[ver][buf] 32KB (128KB) = 147456 B
#define K1_SMEM 147456

__global__ void __launch_bounds__(512) k1_mma(
    const float* __restrict__ b1, const float* __restrict__ lng, const float* __restrict__ lnb)
{
    extern __shared__ __align__(128) char sm1[];
    const uint32_t sb = smem_u32(sm1);
    const int t = threadIdx.x;
    const int lane = t & 31, wid = t >> 5;
    const int wy = wid >> 3, wx = wid & 7;
    const int n = blockIdx.x;
    const long b0 = (long)blockIdx.y * 64;

    __shared__ float b1s[512], lngs[512], lnbs[512];
    __shared__ float redS[8][64], redQ[8][64];
    __shared__ float muS[64], rsS[64];

    b1s[t]  = b1[n * MHD + t];
    lngs[t] = lng[n * MHD + t];
    lnbs[t] = lnb[n * MHD + t];

    const __half* W1hB = g_W1h + ((long)n << 17);
    const __half* W1lB = g_W1l + ((long)n << 17);

    auto load_chunk = [&](int c, int buf) {
        int kb = c * 32;
        {   // A: 512 cp.async
            int ver = t >> 8, i = t & 255, row = i >> 2, cu = i & 3;
            const __half* src = (ver ? g_Zl : g_Zh) + (b0 + row) * DD + kb + cu * 8;
            uint32_t dst = sb + ver * 8192 + buf * 4096 + row * 64 + ((cu ^ ((row >> 1) & 3)) << 4);
            cp16(dst, src);
        }
#pragma unroll
        for (int j = 0; j < 8; j++) {   // B: 4096 cp.async
            int id = t + 512 * j;
            int ver = id >> 11, i = id & 2047, row = i >> 2, cu = i & 3;
            const __half* src = (ver ? W1lB : W1hB) + (long)row * DD + kb + cu * 8;
            uint32_t dst = sb + 16384 + ver * 65536 + buf * 32768 + row * 64
                         + ((cu ^ ((row >> 1) & 3)) << 4);
            cp16(dst, src);
        }
    };

    float acc[2][8][4];
#pragma unroll
    for (int a = 0; a < 2; a++)
#pragma unroll
        for (int b = 0; b < 8; b++)
#pragma unroll
            for (int c = 0; c < 4; c++) acc[a][b][c] = 0.f;

    load_chunk(0, 0);
    CP_COMMIT();
    for (int c = 0; c < 8; c++) {
        int buf = c & 1;
        if (c + 1 < 8) {
            load_chunk(c + 1, (c + 1) & 1);
            CP_COMMIT();
            asm volatile("cp.async.wait_group 1;");
        } else {
            asm volatile("cp.async.wait_group 0;");
        }
        __syncthreads();
        uint32_t aH = sb + buf * 4096;
        uint32_t aL = aH + 8192;
        uint32_t bH = sb + 16384 + buf * 32768;
        uint32_t bL = bH + 65536;
#pragma unroll
        for (int k16 = 0; k16 < 2; k16++) {
            uint32_t ah[2][4], al[2][4];
#pragma unroll
            for (int rf = 0; rf < 2; rf++) {
                int r = wy * 32 + rf * 16 + (lane & 15);
                int cu = k16 * 2 + (lane >> 4);
                uint32_t off = r * 64 + ((cu ^ ((r >> 1) & 3)) << 4);
                ldsm4(ah[rf], aH + off);
                ldsm4(al[rf], aL + off);
            }
#pragma unroll
            for (int bf = 0; bf < 4; bf++) {
                int rb = wx * 64 + bf * 16 + (lane & 15);
                int cu = k16 * 2 + (lane >> 4);
                uint32_t off = rb * 64 + ((cu ^ ((rb >> 1) & 3)) << 4);
                uint32_t bh[4], bl[4];
                ldsm4(bh, bH + off);
                ldsm4(bl, bL + off);
#pragma unroll
                for (int rf = 0; rf < 2; rf++) {
                    mma16816(acc[rf][2 * bf],     ah[rf], bh[0], bh[2]);
                    mma16816(acc[rf][2 * bf + 1], ah[rf], bh[1], bh[3]);
                    mma16816(acc[rf][2 * bf],     ah[rf], bl[0], bl[2]);
                    mma16816(acc[rf][2 * bf + 1], ah[rf], bl[1], bl[3]);
                    mma16816(acc[rf][2 * bf],     al[rf], bh[0], bh[2]);
                    mma16816(acc[rf][2 * bf + 1], al[rf], bh[1], bh[3]);
                }
            }
        }
        __syncthreads();
    }

    // ---- bias + LN stats ----
    float sums[2][2] = {{0.f, 0.f}, {0.f, 0.f}};
    float sqs[2][2]  = {{0.f, 0.f}, {0.f, 0.f}};
#pragma unroll
    for (int rf = 0; rf < 2; rf++)
#pragma unroll
        for (int nf = 0; nf < 8; nf++)
#pragma unroll
            for (int h = 0; h < 2; h++)
#pragma unroll
                for (int p = 0; p < 2; p++) {
                    int col = wx * 64 + nf * 8 + (lane & 3) * 2 + p;
                    float x = acc[rf][nf][h * 2 + p] + b1s[col];
                    acc[rf][nf][h * 2 + p] = x;
                    sums[rf][h] += x;
                    sqs[rf][h]  += x * x;
                }
#pragma unroll
    for (int rf = 0; rf < 2; rf++)
#pragma unroll
        for (int h = 0; h < 2; h++) {
            sums[rf][h] += __shfl_xor_sync(0xffffffffu, sums[rf][h], 1);
            sums[rf][h] += __shfl_xor_sync(0xffffffffu, sums[rf][h], 2);
            sqs[rf][h]  += __shfl_xor_sync(0xffffffffu, sqs[rf][h], 1);
            sqs[rf][h]  += __shfl_xor_sync(0xffffffffu, sqs[rf][h], 2);
        }
    if ((lane & 3) == 0) {
#pragma unroll
        for (int rf = 0; rf < 2; rf++)
#pragma unroll
            for (int h = 0; h < 2; h++) {
                int r = wy * 32 + rf * 16 + h * 8 + (lane >> 2);
                redS[wx][r] = sums[rf][h];
                redQ[wx][r] = sqs[rf][h];
            }
    }
    __syncthreads();
    if (t < 64) {
        float s = 0.f, q = 0.f;
#pragma unroll
        for (int w = 0; w < 8; w++) { s += redS[w][t]; q += redQ[w][t]; }
        float mu = s * (1.f / 512.f);
        float var = q * (1.f / 512.f) - mu * mu;
        muS[t] = mu;
        rsS[t] = rsqrtf(var + 1e-5f);
    }
    __syncthreads();

    // ---- LN scale/shift + GELU + fp16 store ----
#pragma unroll
    for (int rf = 0; rf < 2; rf++)
#pragma unroll
        for (int h = 0; h < 2; h++) {
            int r = wy * 32 + rf * 16 + h * 8 + (lane >> 2);
            float mu = muS[r], rs = rsS[r];
            long grow = b0 + r;
            __half* xh = g_Xh + grow * KCAT + (long)n * MHD;
#pragma unroll
            for (int nf = 0; nf < 8; nf++) {
                int col = wx * 64 + nf * 8 + (lane & 3) * 2;
                float x0 = (acc[rf][nf][h * 2 + 0] - mu) * rs * lngs[col]     + lnbs[col];
                float x1 = (acc[rf][nf][h * 2 + 1] - mu) * rs * lngs[col + 1] + lnbs[col + 1];
                x0 = 0.5f * x0 * (1.f + erff(x0 * 0.70710678118654752f));
                x1 = 0.5f * x1 * (1.f + erff(x1 * 0.70710678118654752f));
                *(__half2*)(xh + col) = __floats2half2_rn(x0, x1);
            }
        }
}

// ============ K2: zt1 = Xh @ G^T + UF via mma.sync fp16 2-term (G hi/lo) ============
// CTA 128x256, 512 threads (warp grid 4x4, warp tile 32x64), K=4096 in 128 chunks of 32.
// 3-stage pipeline. smem: A 3x8KB (24KB) + B 2ver x 3buf x 16KB (96KB) = 122880 B
#define K2_SMEM 122880

__global__ void __launch_bounds__(512) k2_mma(float* __restrict__ out)
{
    extern __shared__ __align__(128) char sm2[];
    const uint32_t sb = smem_u32(sm2);
    const int t = threadIdx.x;
    const int lane = t & 31, wid = t >> 5;
    const int wy = wid >> 2, wx = wid & 3;
    const long bm = (long)blockIdx.x * 128;

    auto load_chunk = [&](int c, int buf) {
        int kb = c * 32;
        {   // A: 512 cp.async (1/thread), 128 rows x 64B
            int row = t >> 2, cu = t & 3;
            const __half* src = g_Xh + (bm + row) * (long)KCAT + kb + cu * 8;
            uint32_t dst = sb + buf * 8192 + row * 64 + ((cu ^ ((row >> 1) & 3)) << 4);
            cp16(dst, src);
        }
#pragma unroll
        for (int j = 0; j < 4; j++) {   // B: 2048 cp.async, 2 ver x 256 rows x 64B
            int id = t + 512 * j;
            int ver = id >> 10, i = id & 1023, row = i >> 2, cu = i & 3;
            const __half* src = (ver ? g_Gl : g_Gh) + (long)row * KCAT + kb + cu * 8;
            uint32_t dst = sb + 24576 + ver * 49152 + buf * 16384 + row * 64
                         + ((cu ^ ((row >> 1) & 3)) << 4);
            cp16(dst, src);
        }
    };

    float acc[2][8][4];
#pragma unroll
    for (int a = 0; a < 2; a++)
#pragma unroll
        for (int b = 0; b < 8; b++)
#pragma unroll
            for (int c = 0; c < 4; c++) acc[a][b][c] = 0.f;

    load_chunk(0, 0); CP_COMMIT();
    load_chunk(1, 1); CP_COMMIT();
    int buf = 0;
    for (int c = 0; c < 128; c++) {
        if (c < 126) asm volatile("cp.async.wait_group 1;");
        else         asm volatile("cp.async.wait_group 0;");
        __syncthreads();
        if (c + 2 < 128) {
            int nb = buf + 2; if (nb >= 3) nb -= 3;
            load_chunk(c + 2, nb);
            CP_COMMIT();
        }
        uint32_t aB = sb + buf * 8192;
        uint32_t bH = sb + 24576 + buf * 16384;
        uint32_t bL = bH + 49152;
#pragma unroll
        for (int k16 = 0; k16 < 2; k16++) {
            uint32_t ah[2][4];
#pragma unroll
            for (int rf = 0; rf < 2; rf++) {
                int r = wy * 32 + rf * 16 + (lane & 15);
                int cu = k16 * 2 + (lane >> 4);
                uint32_t off = r * 64 + ((cu ^ ((r >> 1) & 3)) << 4);
                ldsm4(ah[rf], aB + off);
            }
#pragma unroll
            for (int bf = 0; bf < 4; bf++) {
                int rb = wx * 64 + bf * 16 + (lane & 15);
                int cu = k16 * 2 + (lane >> 4);
                uint32_t off = rb * 64 + ((cu ^ ((rb >> 1) & 3)) << 4);
                uint32_t bh[4], bl[4];
                ldsm4(bh, bH + off);
                ldsm4(bl, bL + off);
#pragma unroll
                for (int rf = 0; rf < 2; rf++) {
                    mma16816(acc[rf][2 * bf],     ah[rf], bh[0], bh[2]);
                    mma16816(acc[rf][2 * bf + 1], ah[rf], bh[1], bh[3]);
                    mma16816(acc[rf][2 * bf],     ah[rf], bl[0], bl[2]);
                    mma16816(acc[rf][2 * bf + 1], ah[rf], bl[1], bl[3]);
                }
            }
        }
        if (++buf == 3) buf = 0;
    }

    // epilogue: + UF, store fp32
#pragma unroll
    for (int rf = 0; rf < 2; rf++)
#pragma unroll
        for (int h = 0; h < 2; h++) {
            long row = bm + wy * 32 + rf * 16 + h * 8 + (lane >> 2);
#pragma unroll
            for (int nf = 0; nf < 8; nf++) {
                int col = wx * 64 + nf * 8 + (lane & 3) * 2;
                float2 u = *(const float2*)(g_UF + row * DD + col);
                float2 o;
                o.x = acc[rf][nf][h * 2 + 0] + u.x;
                o.y = acc[rf][nf][h * 2 + 1] + u.y;
                *(float2*)(out + row * DD + col) = o;
            }
        }
}

// ---------------- K3: yt1 = zt1 @ C^T + dt * ut @ Dm^T ----------------
__global__ void __launch_bounds__(128) kY(
    const float* __restrict__ zt1, float* __restrict__ outY,
    const float* __restrict__ ut, const float* __restrict__ dtp,
    const float* __restrict__ C, const float* __restrict__ Dm)
{
    __shared__ float Cs[20 * 256];
    __shared__ float Dms[20 * 32];
    int t = threadIdx.x;
    for (int i = t; i < 20 * 256; i += 128) Cs[i] = C[i];
    for (int i = t; i < 20 * 32; i += 128) Dms[i] = Dm[i];
    __syncthreads();
    int w = t >> 5, l = t & 31;
    float dtv = dtp[0];
    for (int rr = 0; rr < 8; rr++) {
        long b = (long)blockIdx.x * 32 + w * 8 + rr;
        float zv[8];
#pragma unroll
        for (int i = 0; i < 8; i++) zv[i] = zt1[b * DD + l + 32 * i];
        float dm = 0.f;
        if (l < 20) {
#pragma unroll
            for (int u = 0; u < 32; u++) dm = fmaf(ut[b * UU + u], Dms[l * 32 + u], dm);
            dm *= dtv;
        }
        for (int y = 0; y < 20; y++) {
            float p = 0.f;
#pragma unroll
            for (int i = 0; i < 8; i++) p = fmaf(zv[i], Cs[y * 256 + l + 32 * i], p);
#pragma unroll
            for (int off = 16; off; off >>= 1) p += __shfl_xor_sync(0xffffffffu, p, off);
            if (l == y) outY[b * 20 + y] = p + dm;
        }
    }
}

// ---------------- launch ----------------
extern "C" void kernel_launch(void* const* d_in, const int* in_sizes, int n_in,
                              void* d_out, int out_size) {
    (void)in_sizes; (void)n_in; (void)out_size;
    const float* zt    = (const float*)d_in[0];
    const float* dt    = (const float*)d_in[1];
    const float* ut    = (const float*)d_in[2];
    const float* gates = (const float*)d_in[3];
    const float* W1    = (const float*)d_in[4];
    const float* b1    = (const float*)d_in[5];
    const float* ln_g  = (const float*)d_in[6];
    const float* ln_b  = (const float*)d_in[7];
    const float* W2    = (const float*)d_in[8];
    const float* b2    = (const float*)d_in[9];
    // d_in[10] lam_r, d_in[11] lam_i unused (lambda drops out at h0=0)
    const float* rnnB  = (const float*)d_in[12];
    const float* Wout  = (const float*)d_in[13];
    const float* C     = (const float*)d_in[14];
    const float* Dm    = (const float*)d_in[15];
    float* out = (float*)d_out;                    // [B*D] zt1 then [B*20] yt1

    float* gP; cudaGetSymbolAddress((void**)&gP, g_P);
    float* gG; cudaGetSymbolAddress((void**)&gG, g_G);

    cudaFuncSetAttribute(k1_mma, cudaFuncAttributeMaxDynamicSharedMemorySize, K1_SMEM);
    cudaFuncSetAttribute(k2_mma, cudaFuncAttributeMaxDynamicSharedMemorySize, K2_SMEM);

    // --- precompute needed by k1 first; k1 placed early for ncu capture window ---
    kfold<<<4096, 256>>>(W1, gates);
    ksplitZ<<<16384, 256>>>(zt);
    // P[n] = Bg[n] @ W2[n]
    gemm64<<<dim3(8, 4, NB), 256>>>(rnnB, RNNW, (long)RHD * RNNW,
                                    W2, MHD, (long)RHD * MHD,
                                    gP, MHD, (long)RHD * MHD, RHD);
    // G[d][n*512+h] = W_out[n] @ P[n]
    gemm64<<<dim3(8, 4, NB), 256>>>(Wout, RHD, (long)DD * RHD,
                                    gP, MHD, (long)RHD * MHD,
                                    gG, KCAT, (long)MHD, RHD);
    kGconv<<<4096, 256>>>();

    k1_mma<<<dim3(NB, BSZ / 64), 512, K1_SMEM>>>(b1, ln_g, ln_b);   // launch #5

    kPb<<<256, 256>>>(rnnB, b2);
    kbiasz<<<32, 256>>>(Wout);
    kF<<<1024, 256>>>(Wout, rnnB);
    kUF<<<BSZ / 64, 256>>>(ut, dt);

    k2_mma<<<128, 512, K2_SMEM>>>(out);
    kY<<<BSZ / 32, 128>>>(out, out + (long)BSZ * DD, ut, dt, C, Dm);
}

// round 6
// speedup vs baseline: 3.7241x; 1.2967x over previous
#include <cuda_runtime.h>
#include <cuda_fp16.h>
#include <math.h>
#include <stdint.h>

#define BSZ   16384
#define DD    256
#define UU    32
#define NB    8
#define MHD   512
#define RHD   256
#define KCAT  4096   // NB*MHD
#define RNNW  288    // RHD+UU

// ---------------- static device scratch (no allocations allowed) ----------------
__device__ __align__(16) __half g_W1h[(long)NB * MHD * DD]; // [n][h][d] gate-folded W1, single fp16
__device__ float g_P[(long)NB * RHD * MHD];                 // [n][r][h] = Bg @ W2
__device__ __align__(16) float g_G[(long)DD * KCAT];        // [d][n*512+h]
__device__ __align__(16) __half g_Gh[(long)DD * KCAT];      // single fp16 G
__device__ float g_Pb[NB * RHD];
__device__ float g_F[DD * UU];
__device__ float g_biasz[DD];
__device__ __align__(16) float g_UF[(long)BSZ * DD];
__device__ __align__(16) __half g_Zh[(long)BSZ * DD];
__device__ __align__(16) __half g_Zl[(long)BSZ * DD];
__device__ __align__(16) __half g_Xh[(long)BSZ * KCAT];     // single fp16 X

// ================= helpers (base-arch only: ldmatrix / mma.sync / cp.async) =================
__device__ __forceinline__ uint32_t smem_u32(const void* p) {
    uint32_t a;
    asm("{ .reg .u64 t; cvta.to.shared.u64 t, %1; cvt.u32.u64 %0, t; }" : "=r"(a) : "l"(p));
    return a;
}
__device__ __forceinline__ void cp16(uint32_t dst, const void* src) {
    asm volatile("cp.async.cg.shared.global [%0], [%1], 16;" :: "r"(dst), "l"(src));
}
#define CP_COMMIT() asm volatile("cp.async.commit_group;")
__device__ __forceinline__ void ldsm4(uint32_t (&r)[4], uint32_t addr) {
    asm volatile("ldmatrix.sync.aligned.m8n8.x4.shared.b16 {%0,%1,%2,%3}, [%4];"
                 : "=r"(r[0]), "=r"(r[1]), "=r"(r[2]), "=r"(r[3]) : "r"(addr));
}
__device__ __forceinline__ void mma16816(float (&d)[4], const uint32_t (&a)[4],
                                         uint32_t b0, uint32_t b1) {
    asm volatile("mma.sync.aligned.m16n8k16.row.col.f32.f16.f16.f32 "
                 "{%0,%1,%2,%3}, {%4,%5,%6,%7}, {%8,%9}, {%0,%1,%2,%3};"
                 : "+f"(d[0]), "+f"(d[1]), "+f"(d[2]), "+f"(d[3])
                 : "r"(a[0]), "r"(a[1]), "r"(a[2]), "r"(a[3]), "r"(b0), "r"(b1));
}

// ---------------- fold gates into W1 ([n][h][d]), single fp16 ----------------
__global__ void kfold(const float* __restrict__ W1, const float* __restrict__ gates) {
    int idx = blockIdx.x * 256 + threadIdx.x;     // 2^20 over [n][h][d]
    int n = idx >> 17;
    int d = idx & 255;
    float g = gates[n * DD + d];
    float s = 1.0f / (1.0f + expf(-g));
    g_W1h[idx] = __float2half_rn(W1[idx] * s);
}

// ---------------- split zt into fp16 hi/lo ----------------
__global__ void ksplitZ(const float* __restrict__ zt) {
    long i = (long)blockIdx.x * 256 + threadIdx.x;     // BSZ*DD = 4M
    float v = zt[i];
    __half h = __float2half_rn(v);
    g_Zh[i] = h;
    g_Zl[i] = __float2half_rn(v - __half2float(h));
}

// ---------------- convert G to fp16 ----------------
__global__ void kGconv() {
    long i = (long)blockIdx.x * 256 + threadIdx.x;     // DD*KCAT = 2^20
    g_Gh[i] = __float2half_rn(g_G[i]);
}

// ---------------- batched 64x64 tiled SGEMM (fp32 precompute only) ----------------
__global__ void __launch_bounds__(256) gemm64(
    const float* __restrict__ A, int lda, long sA,
    const float* __restrict__ B, int ldb, long sB,
    float* __restrict__ C, int ldc, long sC, int K)
{
    A += (long)blockIdx.z * sA;
    B += (long)blockIdx.z * sB;
    C += (long)blockIdx.z * sC;
    int bn = blockIdx.x * 64, bm = blockIdx.y * 64;
    __shared__ float As[16][64];
    __shared__ float Bs[16][64];
    int t = threadIdx.x;
    int tr = t >> 4, tc = t & 15;
    float acc[4][4] = {};
    int arow = t >> 2, ak = (t & 3) << 2;
    int bk = t >> 4, boff = (t & 15) << 2;
    for (int k0 = 0; k0 < K; k0 += 16) {
        float4 av = *(const float4*)(A + (long)(bm + arow) * lda + k0 + ak);
        float4 bv = *(const float4*)(B + (long)(k0 + bk) * ldb + bn + boff);
        __syncthreads();
        As[ak + 0][arow] = av.x; As[ak + 1][arow] = av.y;
        As[ak + 2][arow] = av.z; As[ak + 3][arow] = av.w;
        *(float4*)&Bs[bk][boff] = bv;
        __syncthreads();
#pragma unroll
        for (int kk = 0; kk < 16; kk++) {
            float a[4], b[4];
            *(float4*)a = *(float4*)&As[kk][tr << 2];
            *(float4*)b = *(float4*)&Bs[kk][tc << 2];
#pragma unroll
            for (int i = 0; i < 4; i++)
#pragma unroll
                for (int j = 0; j < 4; j++) acc[i][j] = fmaf(a[i], b[j], acc[i][j]);
        }
    }
#pragma unroll
    for (int i = 0; i < 4; i++) {
        float4 o = make_float4(acc[i][0], acc[i][1], acc[i][2], acc[i][3]);
        *(float4*)(C + (long)(bm + (tr << 2) + i) * ldc + bn + (tc << 2)) = o;
    }
}

// ---------------- tiny precompute kernels (warp-per-output) ----------------
__global__ void kPb(const float* __restrict__ rnnB, const float* __restrict__ b2) {
    int g = blockIdx.x * 8 + (threadIdx.x >> 5);      // 2048 outputs
    int lane = threadIdx.x & 31;
    int n = g >> 8, r = g & 255;
    const float* a = rnnB + (long)n * RHD * RNNW + (long)r * RNNW;
    const float* b = b2 + n * RHD;
    float s = 0.f;
#pragma unroll
    for (int i = 0; i < 8; i++) s = fmaf(a[lane + 32 * i], b[lane + 32 * i], s);
#pragma unroll
    for (int off = 16; off; off >>= 1) s += __shfl_xor_sync(0xffffffffu, s, off);
    if (lane == 0) g_Pb[g] = s;
}

__global__ void kbiasz(const float* __restrict__ Wout) {
    int d = blockIdx.x * 8 + (threadIdx.x >> 5);      // 256 outputs
    int lane = threadIdx.x & 31;
    float s = 0.f;
#pragma unroll
    for (int i = 0; i < 64; i++) {
        int idx = lane + 32 * i;                       // 0..2047
        int n = idx >> 8, r = idx & 255;
        s = fmaf(Wout[(long)n * DD * RHD + (long)d * RHD + r], g_Pb[n * RHD + r], s);
    }
#pragma unroll
    for (int off = 16; off; off >>= 1) s += __shfl_xor_sync(0xffffffffu, s, off);
    if (lane == 0) g_biasz[d] = s;
}

__global__ void kF(const float* __restrict__ Wout, const float* __restrict__ rnnB) {
    int g = blockIdx.x * 8 + (threadIdx.x >> 5);      // 8192 outputs
    int lane = threadIdx.x & 31;
    int d = g >> 5, u = g & 31;
    float s = 0.f;
#pragma unroll
    for (int i = 0; i < 64; i++) {
        int idx = lane + 32 * i;
        int n = idx >> 8, r = idx & 255;
        s = fmaf(Wout[(long)n * DD * RHD + (long)d * RHD + r],
                 rnnB[(long)n * RHD * RNNW + (long)r * RNNW + RHD + u], s);
    }
#pragma unroll
    for (int off = 16; off; off >>= 1) s += __shfl_xor_sync(0xffffffffu, s, off);
    if (lane == 0) g_F[d * UU + u] = s;
}

// g_UF[b][d] = biasz[d] + dt * sum_u ut[b][u] * F[d][u]
__global__ void __launch_bounds__(256) kUF(const float* __restrict__ ut, const float* __restrict__ dtp) {
    __shared__ float Fs[UU * DD];
    __shared__ float uts[64 * UU];
    long b0 = (long)blockIdx.x * 64;
    int t = threadIdx.x;
    for (int idx = t; idx < DD * UU; idx += 256) {
        int d = idx >> 5, u = idx & 31;
        Fs[u * DD + d] = g_F[idx];
    }
    for (int idx = t; idx < 64 * UU; idx += 256) uts[idx] = ut[b0 * UU + idx];
    float dtv = dtp[0];
    float bz = g_biasz[t];
    __syncthreads();
    for (int r = 0; r < 64; r++) {
        float s = 0.f;
#pragma unroll
        for (int u = 0; u < UU; u++) s = fmaf(uts[r * UU + u], Fs[u * DD + t], s);
        g_UF[(b0 + r) * DD + t] = fmaf(dtv, s, bz);
    }
}

// ============ K1: Xh = fp16(GELU(LN(zt @ W1f[n]^T + b1))) — 2-term (zt hi/lo, W1f fp16) ============
// CTA 64x512, 512 threads (warp grid 2x8, warp tile 32x64), K=256 in 8 chunks of 32.
// smem: A 2ver x 2buf x 4KB (16KB) + B 2buf x 32KB (64KB) = 81920 B
#define K1_SMEM 81920

__global__ void __launch_bounds__(512) k1_mma(
    const float* __restrict__ b1, const float* __restrict__ lng, const float* __restrict__ lnb)
{
    extern __shared__ __align__(128) char sm1[];
    const uint32_t sb = smem_u32(sm1);
    const int t = threadIdx.x;
    const int lane = t & 31, wid = t >> 5;
    const int wy = wid >> 3, wx = wid & 7;
    const int n = blockIdx.x;
    const long b0 = (long)blockIdx.y * 64;

    __shared__ float b1s[512], lngs[512], lnbs[512];
    __shared__ float redS[8][64], redQ[8][64];
    __shared__ float muS[64], rsS[64];

    b1s[t]  = b1[n * MHD + t];
    lngs[t] = lng[n * MHD + t];
    lnbs[t] = lnb[n * MHD + t];

    const __half* W1B = g_W1h + ((long)n << 17);

    auto load_chunk = [&](int c, int buf) {
        int kb = c * 32;
        {   // A: 512 cp.async (hi/lo versions)
            int ver = t >> 8, i = t & 255, row = i >> 2, cu = i & 3;
            const __half* src = (ver ? g_Zl : g_Zh) + (b0 + row) * DD + kb + cu * 8;
            uint32_t dst = sb + ver * 8192 + buf * 4096 + row * 64 + ((cu ^ ((row >> 1) & 3)) << 4);
            cp16(dst, src);
        }
#pragma unroll
        for (int j = 0; j < 4; j++) {   // B: 2048 cp.async (single fp16)
            int id = t + 512 * j;
            int row = id >> 2, cu = id & 3;
            const __half* src = W1B + (long)row * DD + kb + cu * 8;
            uint32_t dst = sb + 16384 + buf * 32768 + row * 64 + ((cu ^ ((row >> 1) & 3)) << 4);
            cp16(dst, src);
        }
    };

    float acc[2][8][4];
#pragma unroll
    for (int a = 0; a < 2; a++)
#pragma unroll
        for (int b = 0; b < 8; b++)
#pragma unroll
            for (int c = 0; c < 4; c++) acc[a][b][c] = 0.f;

    load_chunk(0, 0);
    CP_COMMIT();
    for (int c = 0; c < 8; c++) {
        int buf = c & 1;
        if (c + 1 < 8) {
            load_chunk(c + 1, (c + 1) & 1);
            CP_COMMIT();
            asm volatile("cp.async.wait_group 1;");
        } else {
            asm volatile("cp.async.wait_group 0;");
        }
        __syncthreads();
        uint32_t aH = sb + buf * 4096;
        uint32_t aL = aH + 8192;
        uint32_t bB = sb + 16384 + buf * 32768;
#pragma unroll
        for (int k16 = 0; k16 < 2; k16++) {
            uint32_t ah[2][4], al[2][4];
#pragma unroll
            for (int rf = 0; rf < 2; rf++) {
                int r = wy * 32 + rf * 16 + (lane & 15);
                int cu = k16 * 2 + (lane >> 4);
                uint32_t off = r * 64 + ((cu ^ ((r >> 1) & 3)) << 4);
                ldsm4(ah[rf], aH + off);
                ldsm4(al[rf], aL + off);
            }
#pragma unroll
            for (int bf = 0; bf < 4; bf++) {
                int rb = wx * 64 + bf * 16 + (lane & 15);
                int cu = k16 * 2 + (lane >> 4);
                uint32_t off = rb * 64 + ((cu ^ ((rb >> 1) & 3)) << 4);
                uint32_t bh[4];
                ldsm4(bh, bB + off);
#pragma unroll
                for (int rf = 0; rf < 2; rf++) {
                    mma16816(acc[rf][2 * bf],     ah[rf], bh[0], bh[2]);
                    mma16816(acc[rf][2 * bf + 1], ah[rf], bh[1], bh[3]);
                    mma16816(acc[rf][2 * bf],     al[rf], bh[0], bh[2]);
                    mma16816(acc[rf][2 * bf + 1], al[rf], bh[1], bh[3]);
                }
            }
        }
        __syncthreads();
    }

    // ---- bias + LN stats ----
    float sums[2][2] = {{0.f, 0.f}, {0.f, 0.f}};
    float sqs[2][2]  = {{0.f, 0.f}, {0.f, 0.f}};
#pragma unroll
    for (int rf = 0; rf < 2; rf++)
#pragma unroll
        for (int nf = 0; nf < 8; nf++)
#pragma unroll
            for (int h = 0; h < 2; h++)
#pragma unroll
                for (int p = 0; p < 2; p++) {
                    int col = wx * 64 + nf * 8 + (lane & 3) * 2 + p;
                    float x = acc[rf][nf][h * 2 + p] + b1s[col];
                    acc[rf][nf][h * 2 + p] = x;
                    sums[rf][h] += x;
                    sqs[rf][h]  += x * x;
                }
#pragma unroll
    for (int rf = 0; rf < 2; rf++)
#pragma unroll
        for (int h = 0; h < 2; h++) {
            sums[rf][h] += __shfl_xor_sync(0xffffffffu, sums[rf][h], 1);
            sums[rf][h] += __shfl_xor_sync(0xffffffffu, sums[rf][h], 2);
            sqs[rf][h]  += __shfl_xor_sync(0xffffffffu, sqs[rf][h], 1);
            sqs[rf][h]  += __shfl_xor_sync(0xffffffffu, sqs[rf][h], 2);
        }
    if ((lane & 3) == 0) {
#pragma unroll
        for (int rf = 0; rf < 2; rf++)
#pragma unroll
            for (int h = 0; h < 2; h++) {
                int r = wy * 32 + rf * 16 + h * 8 + (lane >> 2);
                redS[wx][r] = sums[rf][h];
                redQ[wx][r] = sqs[rf][h];
            }
    }
    __syncthreads();
    if (t < 64) {
        float s = 0.f, q = 0.f;
#pragma unroll
        for (int w = 0; w < 8; w++) { s += redS[w][t]; q += redQ[w][t]; }
        float mu = s * (1.f / 512.f);
        float var = q * (1.f / 512.f) - mu * mu;
        muS[t] = mu;
        rsS[t] = rsqrtf(var + 1e-5f);
    }
    __syncthreads();

    // ---- LN scale/shift + GELU + fp16 store ----
#pragma unroll
    for (int rf = 0; rf < 2; rf++)
#pragma unroll
        for (int h = 0; h < 2; h++) {
            int r = wy * 32 + rf * 16 + h * 8 + (lane >> 2);
            float mu = muS[r], rs = rsS[r];
            long grow = b0 + r;
            __half* xh = g_Xh + grow * KCAT + (long)n * MHD;
#pragma unroll
            for (int nf = 0; nf < 8; nf++) {
                int col = wx * 64 + nf * 8 + (lane & 3) * 2;
                float x0 = (acc[rf][nf][h * 2 + 0] - mu) * rs * lngs[col]     + lnbs[col];
                float x1 = (acc[rf][nf][h * 2 + 1] - mu) * rs * lngs[col + 1] + lnbs[col + 1];
                x0 = 0.5f * x0 * (1.f + erff(x0 * 0.70710678118654752f));
                x1 = 0.5f * x1 * (1.f + erff(x1 * 0.70710678118654752f));
                *(__half2*)(xh + col) = __floats2half2_rn(x0, x1);
            }
        }
}

// ============ K2: zt1 = Xh @ Gh^T + UF — single-term fp16 ============
// CTA 128x256, 512 threads (warp grid 4x4, warp tile 32x64), K=4096 in 128 chunks of 32.
// 3-stage pipeline. smem: A 3x8KB (24KB) + B 3x16KB (48KB) = 73728 B
#define K2_SMEM 73728

__global__ void __launch_bounds__(512) k2_mma(float* __restrict__ out)
{
    extern __shared__ __align__(128) char sm2[];
    const uint32_t sb = smem_u32(sm2);
    const int t = threadIdx.x;
    const int lane = t & 31, wid = t >> 5;
    const int wy = wid >> 2, wx = wid & 3;
    const long bm = (long)blockIdx.x * 128;

    auto load_chunk = [&](int c, int buf) {
        int kb = c * 32;
        {   // A: 512 cp.async, 128 rows x 64B
            int row = t >> 2, cu = t & 3;
            const __half* src = g_Xh + (bm + row) * (long)KCAT + kb + cu * 8;
            uint32_t dst = sb + buf * 8192 + row * 64 + ((cu ^ ((row >> 1) & 3)) << 4);
            cp16(dst, src);
        }
#pragma unroll
        for (int j = 0; j < 2; j++) {   // B: 1024 cp.async, 256 rows x 64B
            int id = t + 512 * j;
            int row = id >> 2, cu = id & 3;
            const __half* src = g_Gh + (long)row * KCAT + kb + cu * 8;
            uint32_t dst = sb + 24576 + buf * 16384 + row * 64 + ((cu ^ ((row >> 1) & 3)) << 4);
            cp16(dst, src);
        }
    };

    float acc[2][8][4];
#pragma unroll
    for (int a = 0; a < 2; a++)
#pragma unroll
        for (int b = 0; b < 8; b++)
#pragma unroll
            for (int c = 0; c < 4; c++) acc[a][b][c] = 0.f;

    load_chunk(0, 0); CP_COMMIT();
    load_chunk(1, 1); CP_COMMIT();
    int buf = 0;
    for (int c = 0; c < 128; c++) {
        if (c < 126) asm volatile("cp.async.wait_group 1;");
        else         asm volatile("cp.async.wait_group 0;");
        __syncthreads();
        if (c + 2 < 128) {
            int nb = buf + 2; if (nb >= 3) nb -= 3;
            load_chunk(c + 2, nb);
            CP_COMMIT();
        }
        uint32_t aB = sb + buf * 8192;
        uint32_t bB = sb + 24576 + buf * 16384;
#pragma unroll
        for (int k16 = 0; k16 < 2; k16++) {
            uint32_t ah[2][4];
#pragma unroll
            for (int rf = 0; rf < 2; rf++) {
                int r = wy * 32 + rf * 16 + (lane & 15);
                int cu = k16 * 2 + (lane >> 4);
                uint32_t off = r * 64 + ((cu ^ ((r >> 1) & 3)) << 4);
                ldsm4(ah[rf], aB + off);
            }
#pragma unroll
            for (int bf = 0; bf < 4; bf++) {
                int rb = wx * 64 + bf * 16 + (lane & 15);
                int cu = k16 * 2 + (lane >> 4);
                uint32_t off = rb * 64 + ((cu ^ ((rb >> 1) & 3)) << 4);
                uint32_t bh[4];
                ldsm4(bh, bB + off);
#pragma unroll
                for (int rf = 0; rf < 2; rf++) {
                    mma16816(acc[rf][2 * bf],     ah[rf], bh[0], bh[2]);
                    mma16816(acc[rf][2 * bf + 1], ah[rf], bh[1], bh[3]);
                }
            }
        }
        if (++buf == 3) buf = 0;
    }

    // epilogue: + UF, store fp32
#pragma unroll
    for (int rf = 0; rf < 2; rf++)
#pragma unroll
        for (int h = 0; h < 2; h++) {
            long row = bm + wy * 32 + rf * 16 + h * 8 + (lane >> 2);
#pragma unroll
            for (int nf = 0; nf < 8; nf++) {
                int col = wx * 64 + nf * 8 + (lane & 3) * 2;
                float2 u = *(const float2*)(g_UF + row * DD + col);
                float2 o;
                o.x = acc[rf][nf][h * 2 + 0] + u.x;
                o.y = acc[rf][nf][h * 2 + 1] + u.y;
                *(float2*)(out + row * DD + col) = o;
            }
        }
}

// ---------------- K3: yt1 = zt1 @ C^T + dt * ut @ Dm^T ----------------
__global__ void __launch_bounds__(128) kY(
    const float* __restrict__ zt1, float* __restrict__ outY,
    const float* __restrict__ ut, const float* __restrict__ dtp,
    const float* __restrict__ C, const float* __restrict__ Dm)
{
    __shared__ float Cs[20 * 256];
    __shared__ float Dms[20 * 32];
    int t = threadIdx.x;
    for (int i = t; i < 20 * 256; i += 128) Cs[i] = C[i];
    for (int i = t; i < 20 * 32; i += 128) Dms[i] = Dm[i];
    __syncthreads();
    int w = t >> 5, l = t & 31;
    float dtv = dtp[0];
    for (int rr = 0; rr < 8; rr++) {
        long b = (long)blockIdx.x * 32 + w * 8 + rr;
        float zv[8];
#pragma unroll
        for (int i = 0; i < 8; i++) zv[i] = zt1[b * DD + l + 32 * i];
        float dm = 0.f;
        if (l < 20) {
#pragma unroll
            for (int u = 0; u < 32; u++) dm = fmaf(ut[b * UU + u], Dms[l * 32 + u], dm);
            dm *= dtv;
        }
        for (int y = 0; y < 20; y++) {
            float p = 0.f;
#pragma unroll
            for (int i = 0; i < 8; i++) p = fmaf(zv[i], Cs[y * 256 + l + 32 * i], p);
#pragma unroll
            for (int off = 16; off; off >>= 1) p += __shfl_xor_sync(0xffffffffu, p, off);
            if (l == y) outY[b * 20 + y] = p + dm;
        }
    }
}

// ---------------- launch ----------------
extern "C" void kernel_launch(void* const* d_in, const int* in_sizes, int n_in,
                              void* d_out, int out_size) {
    (void)in_sizes; (void)n_in; (void)out_size;
    const float* zt    = (const float*)d_in[0];
    const float* dt    = (const float*)d_in[1];
    const float* ut    = (const float*)d_in[2];
    const float* gates = (const float*)d_in[3];
    const float* W1    = (const float*)d_in[4];
    const float* b1    = (const float*)d_in[5];
    const float* ln_g  = (const float*)d_in[6];
    const float* ln_b  = (const float*)d_in[7];
    const float* W2    = (const float*)d_in[8];
    const float* b2    = (const float*)d_in[9];
    // d_in[10] lam_r, d_in[11] lam_i unused (lambda drops out at h0=0)
    const float* rnnB  = (const float*)d_in[12];
    const float* Wout  = (const float*)d_in[13];
    const float* C     = (const float*)d_in[14];
    const float* Dm    = (const float*)d_in[15];
    float* out = (float*)d_out;                    // [B*D] zt1 then [B*20] yt1

    float* gP; cudaGetSymbolAddress((void**)&gP, g_P);
    float* gG; cudaGetSymbolAddress((void**)&gG, g_G);

    cudaFuncSetAttribute(k1_mma, cudaFuncAttributeMaxDynamicSharedMemorySize, K1_SMEM);
    cudaFuncSetAttribute(k2_mma, cudaFuncAttributeMaxDynamicSharedMemorySize, K2_SMEM);

    // k1 deps only, then k1 at launch index 2 (ncu window)
    kfold<<<4096, 256>>>(W1, gates);
    ksplitZ<<<16384, 256>>>(zt);
    k1_mma<<<dim3(NB, BSZ / 64), 512, K1_SMEM>>>(b1, ln_g, ln_b);   // launch #2

    // P[n] = Bg[n] @ W2[n]
    gemm64<<<dim3(8, 4, NB), 256>>>(rnnB, RNNW, (long)RHD * RNNW,
                                    W2, MHD, (long)RHD * MHD,
                                    gP, MHD, (long)RHD * MHD, RHD);
    // G[d][n*512+h] = W_out[n] @ P[n]
    gemm64<<<dim3(8, 4, NB), 256>>>(Wout, RHD, (long)DD * RHD,
                                    gP, MHD, (long)RHD * MHD,
                                    gG, KCAT, (long)MHD, RHD);
    kGconv<<<4096, 256>>>();
    kPb<<<256, 256>>>(rnnB, b2);
    kbiasz<<<32, 256>>>(Wout);
    kF<<<1024, 256>>>(Wout, rnnB);
    kUF<<<BSZ / 64, 256>>>(ut, dt);

    k2_mma<<<128, 512, K2_SMEM>>>(out);
    kY<<<BSZ / 32, 128>>>(out, out + (long)BSZ * DD, ut, dt, C, Dm);
}

// round 7
// speedup vs baseline: 4.6141x; 1.2390x over previous
#include <cuda_runtime.h>
#include <cuda_fp16.h>
#include <math.h>
#include <stdint.h>

#define BSZ   16384
#define DD    256
#define UU    32
#define NB    8
#define MHD   512
#define RHD   256
#define KCAT  4096   // NB*MHD
#define RNNW  288    // RHD+UU
#define NYD   20

// ---------------- static device scratch (no allocations allowed) ----------------
__device__ __align__(16) __half g_W1h[(long)NB * MHD * DD]; // [n][h][d] gate-folded W1, fp16
__device__ float g_P[(long)NB * RHD * MHD];                 // [n][r][h] = Bg @ W2
__device__ __align__(16) float g_G[(long)DD * KCAT];        // [d][n*512+h]
__device__ __align__(16) __half g_Gh[(long)DD * KCAT];      // fp16 G
__device__ float g_Pb[NB * RHD];
__device__ float g_F[DD * UU];
__device__ float g_biasz[DD];
__device__ __align__(16) float g_UF[(long)BSZ * DD];
__device__ __align__(16) __half g_Zh[(long)BSZ * DD];       // fp16 zt
__device__ __align__(16) __half g_Xh[(long)BSZ * KCAT];     // fp16 X

// ================= helpers (base-arch only: ldmatrix / mma.sync / cp.async) =================
__device__ __forceinline__ uint32_t smem_u32(const void* p) {
    uint32_t a;
    asm("{ .reg .u64 t; cvta.to.shared.u64 t, %1; cvt.u32.u64 %0, t; }" : "=r"(a) : "l"(p));
    return a;
}
__device__ __forceinline__ void cp16(uint32_t dst, const void* src) {
    asm volatile("cp.async.cg.shared.global [%0], [%1], 16;" :: "r"(dst), "l"(src));
}
#define CP_COMMIT() asm volatile("cp.async.commit_group;")
__device__ __forceinline__ void ldsm4(uint32_t (&r)[4], uint32_t addr) {
    asm volatile("ldmatrix.sync.aligned.m8n8.x4.shared.b16 {%0,%1,%2,%3}, [%4];"
                 : "=r"(r[0]), "=r"(r[1]), "=r"(r[2]), "=r"(r[3]) : "r"(addr));
}
__device__ __forceinline__ void mma16816(float (&d)[4], const uint32_t (&a)[4],
                                         uint32_t b0, uint32_t b1) {
    asm volatile("mma.sync.aligned.m16n8k16.row.col.f32.f16.f16.f32 "
                 "{%0,%1,%2,%3}, {%4,%5,%6,%7}, {%8,%9}, {%0,%1,%2,%3};"
                 : "+f"(d[0]), "+f"(d[1]), "+f"(d[2]), "+f"(d[3])
                 : "r"(a[0]), "r"(a[1]), "r"(a[2]), "r"(a[3]), "r"(b0), "r"(b1));
}

// ---------------- fold gates into W1 ([n][h][d]), fp16 ----------------
__global__ void kfold(const float* __restrict__ W1, const float* __restrict__ gates) {
    int idx = blockIdx.x * 256 + threadIdx.x;     // 2^20 over [n][h][d]
    int n = idx >> 17;
    int d = idx & 255;
    float g = gates[n * DD + d];
    float s = 1.0f / (1.0f + expf(-g));
    g_W1h[idx] = __float2half_rn(W1[idx] * s);
}

// ---------------- convert zt to fp16 ----------------
__global__ void kZconv(const float* __restrict__ zt) {
    long i = (long)blockIdx.x * 256 + threadIdx.x;     // BSZ*DD = 4M
    g_Zh[i] = __float2half_rn(zt[i]);
}

// ---------------- convert G to fp16 ----------------
__global__ void kGconv() {
    long i = (long)blockIdx.x * 256 + threadIdx.x;     // DD*KCAT = 2^20
    g_Gh[i] = __float2half_rn(g_G[i]);
}

// ---------------- batched 64x64 tiled SGEMM (fp32 precompute only) ----------------
__global__ void __launch_bounds__(256) gemm64(
    const float* __restrict__ A, int lda, long sA,
    const float* __restrict__ B, int ldb, long sB,
    float* __restrict__ C, int ldc, long sC, int K)
{
    A += (long)blockIdx.z * sA;
    B += (long)blockIdx.z * sB;
    C += (long)blockIdx.z * sC;
    int bn = blockIdx.x * 64, bm = blockIdx.y * 64;
    __shared__ float As[16][64];
    __shared__ float Bs[16][64];
    int t = threadIdx.x;
    int tr = t >> 4, tc = t & 15;
    float acc[4][4] = {};
    int arow = t >> 2, ak = (t & 3) << 2;
    int bk = t >> 4, boff = (t & 15) << 2;
    for (int k0 = 0; k0 < K; k0 += 16) {
        float4 av = *(const float4*)(A + (long)(bm + arow) * lda + k0 + ak);
        float4 bv = *(const float4*)(B + (long)(k0 + bk) * ldb + bn + boff);
        __syncthreads();
        As[ak + 0][arow] = av.x; As[ak + 1][arow] = av.y;
        As[ak + 2][arow] = av.z; As[ak + 3][arow] = av.w;
        *(float4*)&Bs[bk][boff] = bv;
        __syncthreads();
#pragma unroll
        for (int kk = 0; kk < 16; kk++) {
            float a[4], b[4];
            *(float4*)a = *(float4*)&As[kk][tr << 2];
            *(float4*)b = *(float4*)&Bs[kk][tc << 2];
#pragma unroll
            for (int i = 0; i < 4; i++)
#pragma unroll
                for (int j = 0; j < 4; j++) acc[i][j] = fmaf(a[i], b[j], acc[i][j]);
        }
    }
#pragma unroll
    for (int i = 0; i < 4; i++) {
        float4 o = make_float4(acc[i][0], acc[i][1], acc[i][2], acc[i][3]);
        *(float4*)(C + (long)(bm + (tr << 2) + i) * ldc + bn + (tc << 2)) = o;
    }
}

// ---------------- tiny precompute kernels (warp-per-output) ----------------
__global__ void kPb(const float* __restrict__ rnnB, const float* __restrict__ b2) {
    int g = blockIdx.x * 8 + (threadIdx.x >> 5);      // 2048 outputs
    int lane = threadIdx.x & 31;
    int n = g >> 8, r = g & 255;
    const float* a = rnnB + (long)n * RHD * RNNW + (long)r * RNNW;
    const float* b = b2 + n * RHD;
    float s = 0.f;
#pragma unroll
    for (int i = 0; i < 8; i++) s = fmaf(a[lane + 32 * i], b[lane + 32 * i], s);
#pragma unroll
    for (int off = 16; off; off >>= 1) s += __shfl_xor_sync(0xffffffffu, s, off);
    if (lane == 0) g_Pb[g] = s;
}

__global__ void kbiasz(const float* __restrict__ Wout) {
    int d = blockIdx.x * 8 + (threadIdx.x >> 5);      // 256 outputs
    int lane = threadIdx.x & 31;
    float s = 0.f;
#pragma unroll
    for (int i = 0; i < 64; i++) {
        int idx = lane + 32 * i;                       // 0..2047
        int n = idx >> 8, r = idx & 255;
        s = fmaf(Wout[(long)n * DD * RHD + (long)d * RHD + r], g_Pb[n * RHD + r], s);
    }
#pragma unroll
    for (int off = 16; off; off >>= 1) s += __shfl_xor_sync(0xffffffffu, s, off);
    if (lane == 0) g_biasz[d] = s;
}

__global__ void kF(const float* __restrict__ Wout, const float* __restrict__ rnnB) {
    int g = blockIdx.x * 8 + (threadIdx.x >> 5);      // 8192 outputs
    int lane = threadIdx.x & 31;
    int d = g >> 5, u = g & 31;
    float s = 0.f;
#pragma unroll
    for (int i = 0; i < 64; i++) {
        int idx = lane + 32 * i;
        int n = idx >> 8, r = idx & 255;
        s = fmaf(Wout[(long)n * DD * RHD + (long)d * RHD + r],
                 rnnB[(long)n * RHD * RNNW + (long)r * RNNW + RHD + u], s);
    }
#pragma unroll
    for (int off = 16; off; off >>= 1) s += __shfl_xor_sync(0xffffffffu, s, off);
    if (lane == 0) g_F[d * UU + u] = s;
}

// g_UF[b][d] = biasz[d] + dt * sum_u ut[b][u] * F[d][u]
__global__ void __launch_bounds__(256) kUF(const float* __restrict__ ut, const float* __restrict__ dtp) {
    __shared__ float Fs[UU * DD];
    __shared__ float uts[64 * UU];
    long b0 = (long)blockIdx.x * 64;
    int t = threadIdx.x;
    for (int idx = t; idx < DD * UU; idx += 256) {
        int d = idx >> 5, u = idx & 31;
        Fs[u * DD + d] = g_F[idx];
    }
    for (int idx = t; idx < 64 * UU; idx += 256) uts[idx] = ut[b0 * UU + idx];
    float dtv = dtp[0];
    float bz = g_biasz[t];
    __syncthreads();
    for (int r = 0; r < 64; r++) {
        float s = 0.f;
#pragma unroll
        for (int u = 0; u < UU; u++) s = fmaf(uts[r * UU + u], Fs[u * DD + t], s);
        g_UF[(b0 + r) * DD + t] = fmaf(dtv, s, bz);
    }
}

// ============ K1: Xh = fp16(GELU(LN(zt @ W1f[n]^T + b1))) — single-term fp16 ============
// CTA 64x512, 512 threads (warp grid 2x8, warp tile 32x64), K=256 in 8 chunks of 32.
// smem: A 2buf x 4KB (8KB) + B 2buf x 32KB (64KB) = 73728 B
#define K1_SMEM 73728

__global__ void __launch_bounds__(512) k1_mma(
    const float* __restrict__ b1, const float* __restrict__ lng, const float* __restrict__ lnb)
{
    extern __shared__ __align__(128) char sm1[];
    const uint32_t sb = smem_u32(sm1);
    const int t = threadIdx.x;
    const int lane = t & 31, wid = t >> 5;
    const int wy = wid >> 3, wx = wid & 7;
    const int n = blockIdx.x;
    const long b0 = (long)blockIdx.y * 64;

    __shared__ float b1s[512], lngs[512], lnbs[512];
    __shared__ float redS[8][64], redQ[8][64];
    __shared__ float muS[64], rsS[64];

    b1s[t]  = b1[n * MHD + t];
    lngs[t] = lng[n * MHD + t];
    lnbs[t] = lnb[n * MHD + t];

    const __half* W1B = g_W1h + ((long)n << 17);

    auto load_chunk = [&](int c, int buf) {
        int kb = c * 32;
        if (t < 256) {   // A: 256 cp.async (single fp16)
            int row = t >> 2, cu = t & 3;
            const __half* src = g_Zh + (b0 + row) * DD + kb + cu * 8;
            uint32_t dst = sb + buf * 4096 + row * 64 + ((cu ^ ((row >> 1) & 3)) << 4);
            cp16(dst, src);
        }
#pragma unroll
        for (int j = 0; j < 4; j++) {   // B: 2048 cp.async
            int id = t + 512 * j;
            int row = id >> 2, cu = id & 3;
            const __half* src = W1B + (long)row * DD + kb + cu * 8;
            uint32_t dst = sb + 8192 + buf * 32768 + row * 64 + ((cu ^ ((row >> 1) & 3)) << 4);
            cp16(dst, src);
        }
    };

    float acc[2][8][4];
#pragma unroll
    for (int a = 0; a < 2; a++)
#pragma unroll
        for (int b = 0; b < 8; b++)
#pragma unroll
            for (int c = 0; c < 4; c++) acc[a][b][c] = 0.f;

    load_chunk(0, 0);
    CP_COMMIT();
    for (int c = 0; c < 8; c++) {
        int buf = c & 1;
        if (c + 1 < 8) {
            load_chunk(c + 1, (c + 1) & 1);
            CP_COMMIT();
            asm volatile("cp.async.wait_group 1;");
        } else {
            asm volatile("cp.async.wait_group 0;");
        }
        __syncthreads();
        uint32_t aB = sb + buf * 4096;
        uint32_t bB = sb + 8192 + buf * 32768;
#pragma unroll
        for (int k16 = 0; k16 < 2; k16++) {
            uint32_t ah[2][4];
#pragma unroll
            for (int rf = 0; rf < 2; rf++) {
                int r = wy * 32 + rf * 16 + (lane & 15);
                int cu = k16 * 2 + (lane >> 4);
                uint32_t off = r * 64 + ((cu ^ ((r >> 1) & 3)) << 4);
                ldsm4(ah[rf], aB + off);
            }
#pragma unroll
            for (int bf = 0; bf < 4; bf++) {
                int rb = wx * 64 + bf * 16 + (lane & 15);
                int cu = k16 * 2 + (lane >> 4);
                uint32_t off = rb * 64 + ((cu ^ ((rb >> 1) & 3)) << 4);
                uint32_t bh[4];
                ldsm4(bh, bB + off);
#pragma unroll
                for (int rf = 0; rf < 2; rf++) {
                    mma16816(acc[rf][2 * bf],     ah[rf], bh[0], bh[2]);
                    mma16816(acc[rf][2 * bf + 1], ah[rf], bh[1], bh[3]);
                }
            }
        }
        __syncthreads();
    }

    // ---- bias + LN stats ----
    float sums[2][2] = {{0.f, 0.f}, {0.f, 0.f}};
    float sqs[2][2]  = {{0.f, 0.f}, {0.f, 0.f}};
#pragma unroll
    for (int rf = 0; rf < 2; rf++)
#pragma unroll
        for (int nf = 0; nf < 8; nf++)
#pragma unroll
            for (int h = 0; h < 2; h++)
#pragma unroll
                for (int p = 0; p < 2; p++) {
                    int col = wx * 64 + nf * 8 + (lane & 3) * 2 + p;
                    float x = acc[rf][nf][h * 2 + p] + b1s[col];
                    acc[rf][nf][h * 2 + p] = x;
                    sums[rf][h] += x;
                    sqs[rf][h]  += x * x;
                }
#pragma unroll
    for (int rf = 0; rf < 2; rf++)
#pragma unroll
        for (int h = 0; h < 2; h++) {
            sums[rf][h] += __shfl_xor_sync(0xffffffffu, sums[rf][h], 1);
            sums[rf][h] += __shfl_xor_sync(0xffffffffu, sums[rf][h], 2);
            sqs[rf][h]  += __shfl_xor_sync(0xffffffffu, sqs[rf][h], 1);
            sqs[rf][h]  += __shfl_xor_sync(0xffffffffu, sqs[rf][h], 2);
        }
    if ((lane & 3) == 0) {
#pragma unroll
        for (int rf = 0; rf < 2; rf++)
#pragma unroll
            for (int h = 0; h < 2; h++) {
                int r = wy * 32 + rf * 16 + h * 8 + (lane >> 2);
                redS[wx][r] = sums[rf][h];
                redQ[wx][r] = sqs[rf][h];
            }
    }
    __syncthreads();
    if (t < 64) {
        float s = 0.f, q = 0.f;
#pragma unroll
        for (int w = 0; w < 8; w++) { s += redS[w][t]; q += redQ[w][t]; }
        float mu = s * (1.f / 512.f);
        float var = q * (1.f / 512.f) - mu * mu;
        muS[t] = mu;
        rsS[t] = rsqrtf(var + 1e-5f);
    }
    __syncthreads();

    // ---- LN scale/shift + GELU + fp16 store ----
#pragma unroll
    for (int rf = 0; rf < 2; rf++)
#pragma unroll
        for (int h = 0; h < 2; h++) {
            int r = wy * 32 + rf * 16 + h * 8 + (lane >> 2);
            float mu = muS[r], rs = rsS[r];
            long grow = b0 + r;
            __half* xh = g_Xh + grow * KCAT + (long)n * MHD;
#pragma unroll
            for (int nf = 0; nf < 8; nf++) {
                int col = wx * 64 + nf * 8 + (lane & 3) * 2;
                float x0 = (acc[rf][nf][h * 2 + 0] - mu) * rs * lngs[col]     + lnbs[col];
                float x1 = (acc[rf][nf][h * 2 + 1] - mu) * rs * lngs[col + 1] + lnbs[col + 1];
                x0 = 0.5f * x0 * (1.f + erff(x0 * 0.70710678118654752f));
                x1 = 0.5f * x1 * (1.f + erff(x1 * 0.70710678118654752f));
                *(__half2*)(xh + col) = __floats2half2_rn(x0, x1);
            }
        }
}

// ============ K2: zt1 = Xh @ Gh^T + UF ; fused yt1 = zt1 @ C^T + dt*ut@Dm^T ============
// CTA 128x256, 512 threads (warp grid 4x4, warp tile 32x64), K=4096 in 128 chunks of 32.
// pipeline smem: A 3x8KB (24KB) + B 3x16KB (48KB) = 73728.
// fused-epilogue smem (reuses pipeline region): zs 128x256 fp16 (64KB) + Cs 256x20 f32 (20KB)
//   + Dms 32x20 f32 (2.5KB) = 88576 B  -> K2_SMEM = 90112
#define K2_SMEM 90112

__global__ void __launch_bounds__(512) k2_mma(
    float* __restrict__ out, float* __restrict__ outY,
    const float* __restrict__ ut, const float* __restrict__ dtp,
    const float* __restrict__ C, const float* __restrict__ Dm)
{
    extern __shared__ __align__(128) char sm2[];
    const uint32_t sb = smem_u32(sm2);
    const int t = threadIdx.x;
    const int lane = t & 31, wid = t >> 5;
    const int wy = wid >> 2, wx = wid & 3;
    const long bm = (long)blockIdx.x * 128;

    auto load_chunk = [&](int c, int buf) {
        int kb = c * 32;
        {   // A: 512 cp.async, 128 rows x 64B
            int row = t >> 2, cu = t & 3;
            const __half* src = g_Xh + (bm + row) * (long)KCAT + kb + cu * 8;
            uint32_t dst = sb + buf * 8192 + row * 64 + ((cu ^ ((row >> 1) & 3)) << 4);
            cp16(dst, src);
        }
#pragma unroll
        for (int j = 0; j < 2; j++) {   // B: 1024 cp.async, 256 rows x 64B
            int id = t + 512 * j;
            int row = id >> 2, cu = id & 3;
            const __half* src = g_Gh + (long)row * KCAT + kb + cu * 8;
            uint32_t dst = sb + 24576 + buf * 16384 + row * 64 + ((cu ^ ((row >> 1) & 3)) << 4);
            cp16(dst, src);
        }
    };

    float acc[2][8][4];
#pragma unroll
    for (int a = 0; a < 2; a++)
#pragma unroll
        for (int b = 0; b < 8; b++)
#pragma unroll
            for (int c = 0; c < 4; c++) acc[a][b][c] = 0.f;

    load_chunk(0, 0); CP_COMMIT();
    load_chunk(1, 1); CP_COMMIT();
    int buf = 0;
    for (int c = 0; c < 128; c++) {
        if (c < 126) asm volatile("cp.async.wait_group 1;");
        else         asm volatile("cp.async.wait_group 0;");
        __syncthreads();
        if (c + 2 < 128) {
            int nb = buf + 2; if (nb >= 3) nb -= 3;
            load_chunk(c + 2, nb);
            CP_COMMIT();
        }
        uint32_t aB = sb + buf * 8192;
        uint32_t bB = sb + 24576 + buf * 16384;
#pragma unroll
        for (int k16 = 0; k16 < 2; k16++) {
            uint32_t ah[2][4];
#pragma unroll
            for (int rf = 0; rf < 2; rf++) {
                int r = wy * 32 + rf * 16 + (lane & 15);
                int cu = k16 * 2 + (lane >> 4);
                uint32_t off = r * 64 + ((cu ^ ((r >> 1) & 3)) << 4);
                ldsm4(ah[rf], aB + off);
            }
#pragma unroll
            for (int bf = 0; bf < 4; bf++) {
                int rb = wx * 64 + bf * 16 + (lane & 15);
                int cu = k16 * 2 + (lane >> 4);
                uint32_t off = rb * 64 + ((cu ^ ((rb >> 1) & 3)) << 4);
                uint32_t bh[4];
                ldsm4(bh, bB + off);
#pragma unroll
                for (int rf = 0; rf < 2; rf++) {
                    mma16816(acc[rf][2 * bf],     ah[rf], bh[0], bh[2]);
                    mma16816(acc[rf][2 * bf + 1], ah[rf], bh[1], bh[3]);
                }
            }
        }
        if (++buf == 3) buf = 0;
    }

    // ---- epilogue: zt1 = acc + UF -> gmem (fp32) + smem (fp16 for y) ----
    __syncthreads();   // pipeline smem now dead; reuse for zs/Cs/Dms
    __half* zs = (__half*)sm2;                       // [128][256] fp16, 64 KB
    float* Cs  = (float*)(sm2 + 65536);              // [256][20] transposed, 20 KB
    float* Dms = (float*)(sm2 + 65536 + 20480);      // [32][20] transposed, 2.5 KB
#pragma unroll
    for (int rf = 0; rf < 2; rf++)
#pragma unroll
        for (int h = 0; h < 2; h++) {
            int lrow = wy * 32 + rf * 16 + h * 8 + (lane >> 2);
            long row = bm + lrow;
#pragma unroll
            for (int nf = 0; nf < 8; nf++) {
                int col = wx * 64 + nf * 8 + (lane & 3) * 2;
                float2 u = *(const float2*)(g_UF + row * DD + col);
                float o0 = acc[rf][nf][h * 2 + 0] + u.x;
                float o1 = acc[rf][nf][h * 2 + 1] + u.y;
                *(float2*)(out + row * DD + col) = make_float2(o0, o1);
                *(__half2*)(zs + lrow * DD + col) = __floats2half2_rn(o0, o1);
            }
        }
    // stage C (transposed) and Dm (transposed)
    for (int i = t; i < NYD * DD; i += 512) {
        int y = i >> 8, d = i & 255;
        Cs[d * NYD + y] = C[i];
    }
    for (int i = t; i < NYD * UU; i += 512) {
        int y = i >> 5, u = i & 31;
        Dms[u * NYD + y] = Dm[i];
    }
    __syncthreads();

    // ---- y: 128 rows x 20 outputs = 2560, 5 per thread ----
    float dtv = dtp[0];
#pragma unroll
    for (int o = 0; o < 5; o++) {
        int idx = t + o * 512;
        int lrow = idx / NYD, y = idx - lrow * NYD;
        const __half2* zr = (const __half2*)(zs + lrow * DD);
        float s = 0.f;
#pragma unroll
        for (int d2 = 0; d2 < DD / 2; d2++) {
            float2 zv = __half22float2(zr[d2]);
            s = fmaf(zv.x, Cs[(2 * d2) * NYD + y], s);
            s = fmaf(zv.y, Cs[(2 * d2 + 1) * NYD + y], s);
        }
        float sm = 0.f;
        const float* ur = ut + (bm + lrow) * UU;
#pragma unroll
        for (int u = 0; u < UU; u++) sm = fmaf(ur[u], Dms[u * NYD + y], sm);
        outY[(bm + lrow) * NYD + y] = s + dtv * sm;
    }
}

// ---------------- launch ----------------
extern "C" void kernel_launch(void* const* d_in, const int* in_sizes, int n_in,
                              void* d_out, int out_size) {
    (void)in_sizes; (void)n_in; (void)out_size;
    const float* zt    = (const float*)d_in[0];
    const float* dt    = (const float*)d_in[1];
    const float* ut    = (const float*)d_in[2];
    const float* gates = (const float*)d_in[3];
    const float* W1    = (const float*)d_in[4];
    const float* b1    = (const float*)d_in[5];
    const float* ln_g  = (const float*)d_in[6];
    const float* ln_b  = (const float*)d_in[7];
    const float* W2    = (const float*)d_in[8];
    const float* b2    = (const float*)d_in[9];
    // d_in[10] lam_r, d_in[11] lam_i unused (lambda drops out at h0=0)
    const float* rnnB  = (const float*)d_in[12];
    const float* Wout  = (const float*)d_in[13];
    const float* C     = (const float*)d_in[14];
    const float* Dm    = (const float*)d_in[15];
    float* out = (float*)d_out;                    // [B*D] zt1 then [B*20] yt1

    float* gP; cudaGetSymbolAddress((void**)&gP, g_P);
    float* gG; cudaGetSymbolAddress((void**)&gG, g_G);

    cudaFuncSetAttribute(k1_mma, cudaFuncAttributeMaxDynamicSharedMemorySize, K1_SMEM);
    cudaFuncSetAttribute(k2_mma, cudaFuncAttributeMaxDynamicSharedMemorySize, K2_SMEM);

    // k1 deps only, then k1 at launch index 2 (ncu window)
    kfold<<<4096, 256>>>(W1, gates);
    kZconv<<<16384, 256>>>(zt);
    k1_mma<<<dim3(NB, BSZ / 64), 512, K1_SMEM>>>(b1, ln_g, ln_b);   // launch #2

    // P[n] = Bg[n] @ W2[n]
    gemm64<<<dim3(8, 4, NB), 256>>>(rnnB, RNNW, (long)RHD * RNNW,
                                    W2, MHD, (long)RHD * MHD,
                                    gP, MHD, (long)RHD * MHD, RHD);
    // G[d][n*512+h] = W_out[n] @ P[n]
    gemm64<<<dim3(8, 4, NB), 256>>>(Wout, RHD, (long)DD * RHD,
                                    gP, MHD, (long)RHD * MHD,
                                    gG, KCAT, (long)MHD, RHD);
    kGconv<<<4096, 256>>>();
    kPb<<<256, 256>>>(rnnB, b2);
    kbiasz<<<32, 256>>>(Wout);
    kF<<<1024, 256>>>(Wout, rnnB);
    kUF<<<BSZ / 64, 256>>>(ut, dt);

    k2_mma<<<128, 512, K2_SMEM>>>(out, out + (long)BSZ * DD, ut, dt, C, Dm);
}

// round 8
// speedup vs baseline: 4.8219x; 1.0450x over previous
#include <cuda_runtime.h>
#include <cuda_fp16.h>
#include <math.h>
#include <stdint.h>

#define BSZ   16384
#define DD    256
#define UU    32
#define NB    8
#define MHD   512
#define RHD   256
#define KCAT  4096   // NB*MHD
#define RNNW  288    // RHD+UU
#define NYD   20

// ---------------- static device scratch (no allocations allowed) ----------------
__device__ __align__(16) __half g_W1h[(long)NB * MHD * DD]; // [n][h][d] gate-folded W1, fp16
__device__ float g_P[(long)NB * RHD * MHD];                 // [n][r][h] = Bg @ W2
__device__ __align__(16) float g_G[(long)DD * KCAT];        // [d][n*512+h]
__device__ __align__(16) __half g_Gh[(long)DD * KCAT];      // fp16 G
__device__ float g_Pb[NB * RHD];
__device__ float g_F[DD * UU];
__device__ float g_biasz[DD];
__device__ __align__(16) float g_UF[(long)BSZ * DD];
__device__ __align__(16) __half g_Zh[(long)BSZ * DD];       // fp16 zt
__device__ __align__(16) __half g_Xh[(long)BSZ * KCAT];     // fp16 X

// ================= helpers (base-arch only: ldmatrix / mma.sync / cp.async) =================
__device__ __forceinline__ uint32_t smem_u32(const void* p) {
    uint32_t a;
    asm("{ .reg .u64 t; cvta.to.shared.u64 t, %1; cvt.u32.u64 %0, t; }" : "=r"(a) : "l"(p));
    return a;
}
__device__ __forceinline__ void cp16(uint32_t dst, const void* src) {
    asm volatile("cp.async.cg.shared.global [%0], [%1], 16;" :: "r"(dst), "l"(src));
}
#define CP_COMMIT() asm volatile("cp.async.commit_group;")
__device__ __forceinline__ void ldsm4(uint32_t (&r)[4], uint32_t addr) {
    asm volatile("ldmatrix.sync.aligned.m8n8.x4.shared.b16 {%0,%1,%2,%3}, [%4];"
                 : "=r"(r[0]), "=r"(r[1]), "=r"(r[2]), "=r"(r[3]) : "r"(addr));
}
__device__ __forceinline__ void mma16816(float (&d)[4], const uint32_t (&a)[4],
                                         uint32_t b0, uint32_t b1) {
    asm volatile("mma.sync.aligned.m16n8k16.row.col.f32.f16.f16.f32 "
                 "{%0,%1,%2,%3}, {%4,%5,%6,%7}, {%8,%9}, {%0,%1,%2,%3};"
                 : "+f"(d[0]), "+f"(d[1]), "+f"(d[2]), "+f"(d[3])
                 : "r"(a[0]), "r"(a[1]), "r"(a[2]), "r"(a[3]), "r"(b0), "r"(b1));
}

// ---------------- fold gates into W1 ([n][h][d]), fp16 ----------------
__global__ void kfold(const float* __restrict__ W1, const float* __restrict__ gates) {
    int idx = blockIdx.x * 256 + threadIdx.x;     // 2^20 over [n][h][d]
    int n = idx >> 17;
    int d = idx & 255;
    float g = gates[n * DD + d];
    float s = 1.0f / (1.0f + expf(-g));
    g_W1h[idx] = __float2half_rn(W1[idx] * s);
}

// ---------------- convert zt to fp16 ----------------
__global__ void kZconv(const float* __restrict__ zt) {
    long i = (long)blockIdx.x * 256 + threadIdx.x;     // BSZ*DD = 4M
    g_Zh[i] = __float2half_rn(zt[i]);
}

// ---------------- convert G to fp16 ----------------
__global__ void kGconv() {
    long i = (long)blockIdx.x * 256 + threadIdx.x;     // DD*KCAT = 2^20
    g_Gh[i] = __float2half_rn(g_G[i]);
}

// ---------------- batched 64x64 tiled SGEMM (fp32 precompute only) ----------------
__global__ void __launch_bounds__(256) gemm64(
    const float* __restrict__ A, int lda, long sA,
    const float* __restrict__ B, int ldb, long sB,
    float* __restrict__ C, int ldc, long sC, int K)
{
    A += (long)blockIdx.z * sA;
    B += (long)blockIdx.z * sB;
    C += (long)blockIdx.z * sC;
    int bn = blockIdx.x * 64, bm = blockIdx.y * 64;
    __shared__ float As[16][64];
    __shared__ float Bs[16][64];
    int t = threadIdx.x;
    int tr = t >> 4, tc = t & 15;
    float acc[4][4] = {};
    int arow = t >> 2, ak = (t & 3) << 2;
    int bk = t >> 4, boff = (t & 15) << 2;
    for (int k0 = 0; k0 < K; k0 += 16) {
        float4 av = *(const float4*)(A + (long)(bm + arow) * lda + k0 + ak);
        float4 bv = *(const float4*)(B + (long)(k0 + bk) * ldb + bn + boff);
        __syncthreads();
        As[ak + 0][arow] = av.x; As[ak + 1][arow] = av.y;
        As[ak + 2][arow] = av.z; As[ak + 3][arow] = av.w;
        *(float4*)&Bs[bk][boff] = bv;
        __syncthreads();
#pragma unroll
        for (int kk = 0; kk < 16; kk++) {
            float a[4], b[4];
            *(float4*)a = *(float4*)&As[kk][tr << 2];
            *(float4*)b = *(float4*)&Bs[kk][tc << 2];
#pragma unroll
            for (int i = 0; i < 4; i++)
#pragma unroll
                for (int j = 0; j < 4; j++) acc[i][j] = fmaf(a[i], b[j], acc[i][j]);
        }
    }
#pragma unroll
    for (int i = 0; i < 4; i++) {
        float4 o = make_float4(acc[i][0], acc[i][1], acc[i][2], acc[i][3]);
        *(float4*)(C + (long)(bm + (tr << 2) + i) * ldc + bn + (tc << 2)) = o;
    }
}

// ---------------- tiny precompute kernels (warp-per-output) ----------------
__global__ void kPb(const float* __restrict__ rnnB, const float* __restrict__ b2) {
    int g = blockIdx.x * 8 + (threadIdx.x >> 5);      // 2048 outputs
    int lane = threadIdx.x & 31;
    int n = g >> 8, r = g & 255;
    const float* a = rnnB + (long)n * RHD * RNNW + (long)r * RNNW;
    const float* b = b2 + n * RHD;
    float s = 0.f;
#pragma unroll
    for (int i = 0; i < 8; i++) s = fmaf(a[lane + 32 * i], b[lane + 32 * i], s);
#pragma unroll
    for (int off = 16; off; off >>= 1) s += __shfl_xor_sync(0xffffffffu, s, off);
    if (lane == 0) g_Pb[g] = s;
}

__global__ void kbiasz(const float* __restrict__ Wout) {
    int d = blockIdx.x * 8 + (threadIdx.x >> 5);      // 256 outputs
    int lane = threadIdx.x & 31;
    float s = 0.f;
#pragma unroll
    for (int i = 0; i < 64; i++) {
        int idx = lane + 32 * i;                       // 0..2047
        int n = idx >> 8, r = idx & 255;
        s = fmaf(Wout[(long)n * DD * RHD + (long)d * RHD + r], g_Pb[n * RHD + r], s);
    }
#pragma unroll
    for (int off = 16; off; off >>= 1) s += __shfl_xor_sync(0xffffffffu, s, off);
    if (lane == 0) g_biasz[d] = s;
}

__global__ void kF(const float* __restrict__ Wout, const float* __restrict__ rnnB) {
    int g = blockIdx.x * 8 + (threadIdx.x >> 5);      // 8192 outputs
    int lane = threadIdx.x & 31;
    int d = g >> 5, u = g & 31;
    float s = 0.f;
#pragma unroll
    for (int i = 0; i < 64; i++) {
        int idx = lane + 32 * i;
        int n = idx >> 8, r = idx & 255;
        s = fmaf(Wout[(long)n * DD * RHD + (long)d * RHD + r],
                 rnnB[(long)n * RHD * RNNW + (long)r * RNNW + RHD + u], s);
    }
#pragma unroll
    for (int off = 16; off; off >>= 1) s += __shfl_xor_sync(0xffffffffu, s, off);
    if (lane == 0) g_F[d * UU + u] = s;
}

// g_UF[b][d] = biasz[d] + dt * sum_u ut[b][u] * F[d][u]
__global__ void __launch_bounds__(256) kUF(const float* __restrict__ ut, const float* __restrict__ dtp) {
    __shared__ float Fs[UU * DD];
    __shared__ float uts[64 * UU];
    long b0 = (long)blockIdx.x * 64;
    int t = threadIdx.x;
    for (int idx = t; idx < DD * UU; idx += 256) {
        int d = idx >> 5, u = idx & 31;
        Fs[u * DD + d] = g_F[idx];
    }
    for (int idx = t; idx < 64 * UU; idx += 256) uts[idx] = ut[b0 * UU + idx];
    float dtv = dtp[0];
    float bz = g_biasz[t];
    __syncthreads();
    for (int r = 0; r < 64; r++) {
        float s = 0.f;
#pragma unroll
        for (int u = 0; u < UU; u++) s = fmaf(uts[r * UU + u], Fs[u * DD + t], s);
        g_UF[(b0 + r) * DD + t] = fmaf(dtv, s, bz);
    }
}

// ============ K1: Xh = fp16(GELU(LN(zt @ W1f[n]^T + b1))) — single-term fp16 ============
// CTA 64x512, 512 threads (warp grid 2x8, warp tile 32x64), K=256 in 8 chunks of 32.
// smem: A 2buf x 4KB (8KB) + B 2buf x 32KB (64KB) = 73728 B
#define K1_SMEM 73728

__global__ void __launch_bounds__(512) k1_mma(
    const float* __restrict__ b1, const float* __restrict__ lng, const float* __restrict__ lnb)
{
    extern __shared__ __align__(128) char sm1[];
    const uint32_t sb = smem_u32(sm1);
    const int t = threadIdx.x;
    const int lane = t & 31, wid = t >> 5;
    const int wy = wid >> 3, wx = wid & 7;
    const int n = blockIdx.x;
    const long b0 = (long)blockIdx.y * 64;

    __shared__ float b1s[512], lngs[512], lnbs[512];
    __shared__ float redS[8][64], redQ[8][64];
    __shared__ float muS[64], rsS[64];

    b1s[t]  = b1[n * MHD + t];
    lngs[t] = lng[n * MHD + t];
    lnbs[t] = lnb[n * MHD + t];

    const __half* W1B = g_W1h + ((long)n << 17);

    auto load_chunk = [&](int c, int buf) {
        int kb = c * 32;
        if (t < 256) {   // A: 256 cp.async (single fp16)
            int row = t >> 2, cu = t & 3;
            const __half* src = g_Zh + (b0 + row) * DD + kb + cu * 8;
            uint32_t dst = sb + buf * 4096 + row * 64 + ((cu ^ ((row >> 1) & 3)) << 4);
            cp16(dst, src);
        }
#pragma unroll
        for (int j = 0; j < 4; j++) {   // B: 2048 cp.async
            int id = t + 512 * j;
            int row = id >> 2, cu = id & 3;
            const __half* src = W1B + (long)row * DD + kb + cu * 8;
            uint32_t dst = sb + 8192 + buf * 32768 + row * 64 + ((cu ^ ((row >> 1) & 3)) << 4);
            cp16(dst, src);
        }
    };

    float acc[2][8][4];
#pragma unroll
    for (int a = 0; a < 2; a++)
#pragma unroll
        for (int b = 0; b < 8; b++)
#pragma unroll
            for (int c = 0; c < 4; c++) acc[a][b][c] = 0.f;

    load_chunk(0, 0);
    CP_COMMIT();
    for (int c = 0; c < 8; c++) {
        int buf = c & 1;
        if (c + 1 < 8) {
            load_chunk(c + 1, (c + 1) & 1);
            CP_COMMIT();
            asm volatile("cp.async.wait_group 1;");
        } else {
            asm volatile("cp.async.wait_group 0;");
        }
        __syncthreads();
        uint32_t aB = sb + buf * 4096;
        uint32_t bB = sb + 8192 + buf * 32768;
#pragma unroll
        for (int k16 = 0; k16 < 2; k16++) {
            uint32_t ah[2][4];
#pragma unroll
            for (int rf = 0; rf < 2; rf++) {
                int r = wy * 32 + rf * 16 + (lane & 15);
                int cu = k16 * 2 + (lane >> 4);
                uint32_t off = r * 64 + ((cu ^ ((r >> 1) & 3)) << 4);
                ldsm4(ah[rf], aB + off);
            }
#pragma unroll
            for (int bf = 0; bf < 4; bf++) {
                int rb = wx * 64 + bf * 16 + (lane & 15);
                int cu = k16 * 2 + (lane >> 4);
                uint32_t off = rb * 64 + ((cu ^ ((rb >> 1) & 3)) << 4);
                uint32_t bh[4];
                ldsm4(bh, bB + off);
#pragma unroll
                for (int rf = 0; rf < 2; rf++) {
                    mma16816(acc[rf][2 * bf],     ah[rf], bh[0], bh[2]);
                    mma16816(acc[rf][2 * bf + 1], ah[rf], bh[1], bh[3]);
                }
            }
        }
        __syncthreads();
    }

    // ---- bias + LN stats ----
    float sums[2][2] = {{0.f, 0.f}, {0.f, 0.f}};
    float sqs[2][2]  = {{0.f, 0.f}, {0.f, 0.f}};
#pragma unroll
    for (int rf = 0; rf < 2; rf++)
#pragma unroll
        for (int nf = 0; nf < 8; nf++)
#pragma unroll
            for (int h = 0; h < 2; h++)
#pragma unroll
                for (int p = 0; p < 2; p++) {
                    int col = wx * 64 + nf * 8 + (lane & 3) * 2 + p;
                    float x = acc[rf][nf][h * 2 + p] + b1s[col];
                    acc[rf][nf][h * 2 + p] = x;
                    sums[rf][h] += x;
                    sqs[rf][h]  += x * x;
                }
#pragma unroll
    for (int rf = 0; rf < 2; rf++)
#pragma unroll
        for (int h = 0; h < 2; h++) {
            sums[rf][h] += __shfl_xor_sync(0xffffffffu, sums[rf][h], 1);
            sums[rf][h] += __shfl_xor_sync(0xffffffffu, sums[rf][h], 2);
            sqs[rf][h]  += __shfl_xor_sync(0xffffffffu, sqs[rf][h], 1);
            sqs[rf][h]  += __shfl_xor_sync(0xffffffffu, sqs[rf][h], 2);
        }
    if ((lane & 3) == 0) {
#pragma unroll
        for (int rf = 0; rf < 2; rf++)
#pragma unroll
            for (int h = 0; h < 2; h++) {
                int r = wy * 32 + rf * 16 + h * 8 + (lane >> 2);
                redS[wx][r] = sums[rf][h];
                redQ[wx][r] = sqs[rf][h];
            }
    }
    __syncthreads();
    if (t < 64) {
        float s = 0.f, q = 0.f;
#pragma unroll
        for (int w = 0; w < 8; w++) { s += redS[w][t]; q += redQ[w][t]; }
        float mu = s * (1.f / 512.f);
        float var = q * (1.f / 512.f) - mu * mu;
        muS[t] = mu;
        rsS[t] = rsqrtf(var + 1e-5f);
    }
    __syncthreads();

    // ---- LN scale/shift + GELU + fp16 store ----
#pragma unroll
    for (int rf = 0; rf < 2; rf++)
#pragma unroll
        for (int h = 0; h < 2; h++) {
            int r = wy * 32 + rf * 16 + h * 8 + (lane >> 2);
            float mu = muS[r], rs = rsS[r];
            long grow = b0 + r;
            __half* xh = g_Xh + grow * KCAT + (long)n * MHD;
#pragma unroll
            for (int nf = 0; nf < 8; nf++) {
                int col = wx * 64 + nf * 8 + (lane & 3) * 2;
                float x0 = (acc[rf][nf][h * 2 + 0] - mu) * rs * lngs[col]     + lnbs[col];
                float x1 = (acc[rf][nf][h * 2 + 1] - mu) * rs * lngs[col + 1] + lnbs[col + 1];
                x0 = 0.5f * x0 * (1.f + erff(x0 * 0.70710678118654752f));
                x1 = 0.5f * x1 * (1.f + erff(x1 * 0.70710678118654752f));
                *(__half2*)(xh + col) = __floats2half2_rn(x0, x1);
            }
        }
}

// ============ K2: zt1 = Xh @ Gh^T + UF ; fused yt1 = zt1 @ C^T + dt*ut@Dm^T ============
// CTA 128x256, 512 threads (warp grid 4x4, warp tile 32x64), K=4096 in 128 chunks of 32.
// pipeline smem: A 3x8KB (24KB) + B 3x16KB (48KB) = 73728.
// fused-epilogue smem (reuses pipeline region): zs 128x256 fp16 (64KB) + Cs 256x20 f32 (20KB)
//   + Dms 32x20 f32 (2.5KB) = 88576 B  -> K2_SMEM = 90112
#define K2_SMEM 90112

__global__ void __launch_bounds__(512) k2_mma(
    float* __restrict__ out, float* __restrict__ outY,
    const float* __restrict__ ut, const float* __restrict__ dtp,
    const float* __restrict__ C, const float* __restrict__ Dm)
{
    extern __shared__ __align__(128) char sm2[];
    const uint32_t sb = smem_u32(sm2);
    const int t = threadIdx.x;
    const int lane = t & 31, wid = t >> 5;
    const int wy = wid >> 2, wx = wid & 3;
    const long bm = (long)blockIdx.x * 128;

    auto load_chunk = [&](int c, int buf) {
        int kb = c * 32;
        {   // A: 512 cp.async, 128 rows x 64B
            int row = t >> 2, cu = t & 3;
            const __half* src = g_Xh + (bm + row) * (long)KCAT + kb + cu * 8;
            uint32_t dst = sb + buf * 8192 + row * 64 + ((cu ^ ((row >> 1) & 3)) << 4);
            cp16(dst, src);
        }
#pragma unroll
        for (int j = 0; j < 2; j++) {   // B: 1024 cp.async, 256 rows x 64B
            int id = t + 512 * j;
            int row = id >> 2, cu = id & 3;
            const __half* src = g_Gh + (long)row * KCAT + kb + cu * 8;
            uint32_t dst = sb + 24576 + buf * 16384 + row * 64 + ((cu ^ ((row >> 1) & 3)) << 4);
            cp16(dst, src);
        }
    };

    float acc[2][8][4];
#pragma unroll
    for (int a = 0; a < 2; a++)
#pragma unroll
        for (int b = 0; b < 8; b++)
#pragma unroll
            for (int c = 0; c < 4; c++) acc[a][b][c] = 0.f;

    load_chunk(0, 0); CP_COMMIT();
    load_chunk(1, 1); CP_COMMIT();
    int buf = 0;
    for (int c = 0; c < 128; c++) {
        if (c < 126) asm volatile("cp.async.wait_group 1;");
        else         asm volatile("cp.async.wait_group 0;");
        __syncthreads();
        if (c + 2 < 128) {
            int nb = buf + 2; if (nb >= 3) nb -= 3;
            load_chunk(c + 2, nb);
            CP_COMMIT();
        }
        uint32_t aB = sb + buf * 8192;
        uint32_t bB = sb + 24576 + buf * 16384;
#pragma unroll
        for (int k16 = 0; k16 < 2; k16++) {
            uint32_t ah[2][4];
#pragma unroll
            for (int rf = 0; rf < 2; rf++) {
                int r = wy * 32 + rf * 16 + (lane & 15);
                int cu = k16 * 2 + (lane >> 4);
                uint32_t off = r * 64 + ((cu ^ ((r >> 1) & 3)) << 4);
                ldsm4(ah[rf], aB + off);
            }
#pragma unroll
            for (int bf = 0; bf < 4; bf++) {
                int rb = wx * 64 + bf * 16 + (lane & 15);
                int cu = k16 * 2 + (lane >> 4);
                uint32_t off = rb * 64 + ((cu ^ ((rb >> 1) & 3)) << 4);
                uint32_t bh[4];
                ldsm4(bh, bB + off);
#pragma unroll
                for (int rf = 0; rf < 2; rf++) {
                    mma16816(acc[rf][2 * bf],     ah[rf], bh[0], bh[2]);
                    mma16816(acc[rf][2 * bf + 1], ah[rf], bh[1], bh[3]);
                }
            }
        }
        if (++buf == 3) buf = 0;
    }

    // ---- epilogue: zt1 = acc + UF -> gmem (fp32) + smem (fp16 for y) ----
    __syncthreads();   // pipeline smem now dead; reuse for zs/Cs/Dms
    __half* zs = (__half*)sm2;                       // [128][256] fp16, 64 KB
    float* Cs  = (float*)(sm2 + 65536);              // [256][20] transposed, 20 KB
    float* Dms = (float*)(sm2 + 65536 + 20480);      // [32][20] transposed, 2.5 KB
#pragma unroll
    for (int rf = 0; rf < 2; rf++)
#pragma unroll
        for (int h = 0; h < 2; h++) {
            int lrow = wy * 32 + rf * 16 + h * 8 + (lane >> 2);
            long row = bm + lrow;
#pragma unroll
            for (int nf = 0; nf < 8; nf++) {
                int col = wx * 64 + nf * 8 + (lane & 3) * 2;
                float2 u = *(const float2*)(g_UF + row * DD + col);
                float o0 = acc[rf][nf][h * 2 + 0] + u.x;
                float o1 = acc[rf][nf][h * 2 + 1] + u.y;
                *(float2*)(out + row * DD + col) = make_float2(o0, o1);
                *(__half2*)(zs + lrow * DD + col) = __floats2half2_rn(o0, o1);
            }
        }
    // stage C (transposed) and Dm (transposed)
    for (int i = t; i < NYD * DD; i += 512) {
        int y = i >> 8, d = i & 255;
        Cs[d * NYD + y] = C[i];
    }
    for (int i = t; i < NYD * UU; i += 512) {
        int y = i >> 5, u = i & 31;
        Dms[u * NYD + y] = Dm[i];
    }
    __syncthreads();

    // ---- y: 128 rows x 20 outputs = 2560, 5 per thread ----
    float dtv = dtp[0];
#pragma unroll
    for (int o = 0; o < 5; o++) {
        int idx = t + o * 512;
        int lrow = idx / NYD, y = idx - lrow * NYD;
        const __half2* zr = (const __half2*)(zs + lrow * DD);
        float s = 0.f;
#pragma unroll
        for (int d2 = 0; d2 < DD / 2; d2++) {
            float2 zv = __half22float2(zr[d2]);
            s = fmaf(zv.x, Cs[(2 * d2) * NYD + y], s);
            s = fmaf(zv.y, Cs[(2 * d2 + 1) * NYD + y], s);
        }
        float sm = 0.f;
        const float* ur = ut + (bm + lrow) * UU;
#pragma unroll
        for (int u = 0; u < UU; u++) sm = fmaf(ur[u], Dms[u * NYD + y], sm);
        outY[(bm + lrow) * NYD + y] = s + dtv * sm;
    }
}

// ---------------- launch ----------------
extern "C" void kernel_launch(void* const* d_in, const int* in_sizes, int n_in,
                              void* d_out, int out_size) {
    (void)in_sizes; (void)n_in; (void)out_size;
    const float* zt    = (const float*)d_in[0];
    const float* dt    = (const float*)d_in[1];
    const float* ut    = (const float*)d_in[2];
    const float* gates = (const float*)d_in[3];
    const float* W1    = (const float*)d_in[4];
    const float* b1    = (const float*)d_in[5];
    const float* ln_g  = (const float*)d_in[6];
    const float* ln_b  = (const float*)d_in[7];
    const float* W2    = (const float*)d_in[8];
    const float* b2    = (const float*)d_in[9];
    // d_in[10] lam_r, d_in[11] lam_i unused (lambda drops out at h0=0)
    const float* rnnB  = (const float*)d_in[12];
    const float* Wout  = (const float*)d_in[13];
    const float* C     = (const float*)d_in[14];
    const float* Dm    = (const float*)d_in[15];
    float* out = (float*)d_out;                    // [B*D] zt1 then [B*20] yt1

    float* gP; cudaGetSymbolAddress((void**)&gP, g_P);
    float* gG; cudaGetSymbolAddress((void**)&gG, g_G);

    cudaFuncSetAttribute(k1_mma, cudaFuncAttributeMaxDynamicSharedMemorySize, K1_SMEM);
    cudaFuncSetAttribute(k2_mma, cudaFuncAttributeMaxDynamicSharedMemorySize, K2_SMEM);

    // lazily-created side stream + fork/join events (host objects only; created on the
    // first, pre-capture call — no device memory, identical work every call)
    static cudaStream_t s2 = nullptr;
    static cudaEvent_t evF = nullptr, evJ = nullptr;
    if (s2 == nullptr) {
        cudaStreamCreateWithFlags(&s2, cudaStreamNonBlocking);
        cudaEventCreateWithFlags(&evF, cudaEventDisableTiming);
        cudaEventCreateWithFlags(&evJ, cudaEventDisableTiming);
    }

    // fork: side stream runs the k2-only precompute chain concurrently with k1
    cudaEventRecord(evF, 0);
    cudaStreamWaitEvent(s2, evF, 0);

    // side stream: G / biasz / F / UF chain (independent of k1)
    gemm64<<<dim3(8, 4, NB), 256, 0, s2>>>(rnnB, RNNW, (long)RHD * RNNW,
                                           W2, MHD, (long)RHD * MHD,
                                           gP, MHD, (long)RHD * MHD, RHD);
    gemm64<<<dim3(8, 4, NB), 256, 0, s2>>>(Wout, RHD, (long)DD * RHD,
                                           gP, MHD, (long)RHD * MHD,
                                           gG, KCAT, (long)MHD, RHD);
    kGconv<<<4096, 256, 0, s2>>>();
    kPb<<<256, 256, 0, s2>>>(rnnB, b2);
    kbiasz<<<32, 256, 0, s2>>>(Wout);
    kF<<<1024, 256, 0, s2>>>(Wout, rnnB);
    kUF<<<BSZ / 64, 256, 0, s2>>>(ut, dt);
    cudaEventRecord(evJ, s2);

    // main stream: k1 path
    kfold<<<4096, 256>>>(W1, gates);
    kZconv<<<16384, 256>>>(zt);
    k1_mma<<<dim3(NB, BSZ / 64), 512, K1_SMEM>>>(b1, ln_g, ln_b);

    // join, then k2 (+fused y)
    cudaStreamWaitEvent(0, evJ, 0);
    k2_mma<<<128, 512, K2_SMEM>>>(out, out + (long)BSZ * DD, ut, dt, C, Dm);
}